// round 11
// baseline (speedup 1.0000x reference)
#include <cuda_runtime.h>
#include <cuda_fp16.h>
#include <cstddef>
#include <cstdint>

#define Bn   4
#define Nn   8192
#define Cn   512
#define DHn  128
#define QK_SPLIT 16

// ---------------- scratch (device globals) ---------------------------------
__device__ __align__(128) __half g_xh  [(size_t)Bn * Nn * Cn];
__device__ __align__(128) __half g_wqh [1536 * 512];
__device__ __align__(128) __half g_woh [512 * 512];
__device__ __align__(128) __half g_qkv [(size_t)Bn * 1024 * Nn];   // q,k channel-major
__device__ __align__(128) __half g_vt  [(size_t)Bn * Nn * Cn];     // v token-major
__device__ __align__(128) float  g_nP  [Bn * 64 * 1024];           // norm partials
__device__ __align__(128) float  g_inv [Bn * 1024];
__device__ __align__(128) float  g_attnP[16 * QK_SPLIT * DHn * DHn];
__device__ __align__(128) __half g_attnT[16 * DHn * DHn];          // [bh][d][c]
__device__ __align__(128) __half g_M   [Bn * Cn * Cn];             // fused Wout@attn

// ---------------- PTX helpers ----------------------------------------------
__device__ __forceinline__ uint32_t sptr(const void* p) {
    return (uint32_t)__cvta_generic_to_shared(p);
}
#define CPA(dst, src) asm volatile("cp.async.cg.shared.global [%0],[%1],16;\n" \
                                   :: "r"(dst), "l"(src))
#define CPC() asm volatile("cp.async.commit_group;\n")
#define CPW0() asm volatile("cp.async.wait_group 0;\n")
#define CPW1() asm volatile("cp.async.wait_group 1;\n")

__device__ __forceinline__ void ldmx4(uint32_t* r, uint32_t a) {
    asm volatile("ldmatrix.sync.aligned.m8n8.x4.shared.b16 {%0,%1,%2,%3},[%4];"
                 : "=r"(r[0]), "=r"(r[1]), "=r"(r[2]), "=r"(r[3]) : "r"(a));
}
__device__ __forceinline__ void mma16816(float* c, const uint32_t* a, const uint32_t* b) {
    asm volatile(
        "mma.sync.aligned.m16n8k16.row.col.f32.f16.f16.f32 "
        "{%0,%1,%2,%3},{%4,%5,%6,%7},{%8,%9},{%0,%1,%2,%3};"
        : "+f"(c[0]), "+f"(c[1]), "+f"(c[2]), "+f"(c[3])
        : "r"(a[0]), "r"(a[1]), "r"(a[2]), "r"(a[3]), "r"(b[0]), "r"(b[1]));
}

// ---------------------------------------------------------------------------
// Pipelined 64(m) x 128(n) GEMM mainloop, BK=64, 2-stage ring, one barrier
// per iter. 128 threads = 4 warps, each 64x32 warp tile (wm=0, wn=wid*32).
// Stage: A 64 rows x 144B at +0 (9216B), B 128 rows x 144B at +9216.
// 3 CTAs/SM. Requires K % 64 == 0 and K/64 >= 2.
// ---------------------------------------------------------------------------
#define STAGE_BYTES 27648
#define BIG_SMEM    (2 * STAGE_BYTES)   // 55296

#define GEMM_MAINLOOP(A, B, K, lda, ldb, m0, n0)                               \
    const uint32_t s0 = sptr(dsm);                                             \
    const int tid  = threadIdx.x;                                              \
    const int lane = tid & 31;                                                 \
    const int wid  = tid >> 5;                                                 \
    const int wn   = wid * 32;                                                 \
    float acc[4][4][4];                                                        \
    _Pragma("unroll") for (int i = 0; i < 4; i++)                              \
    _Pragma("unroll") for (int j = 0; j < 4; j++)                              \
    _Pragma("unroll") for (int t = 0; t < 4; t++) acc[i][j][t] = 0.f;          \
    const int lrow = tid >> 3;           /* 0..15 */                           \
    const int lc16 = tid & 7;                                                  \
    const __half* Ag = (A) + (size_t)((m0) + lrow) * (lda) + lc16 * 8;         \
    const __half* Bg = (B) + (size_t)((n0) + lrow) * (ldb) + lc16 * 8;         \
    auto load_stage = [&](int stg, int k0) {                                   \
        const uint32_t ad = s0 + stg * STAGE_BYTES + lrow * 144 + lc16 * 16;   \
        const uint32_t bd = ad + 9216;                                         \
        _Pragma("unroll") for (int u = 0; u < 4; u++)                          \
            CPA(ad + u * (16 * 144), Ag + (size_t)(u * 16) * (lda) + k0);      \
        _Pragma("unroll") for (int u = 0; u < 8; u++)                          \
            CPA(bd + u * (16 * 144), Bg + (size_t)(u * 16) * (ldb) + k0);      \
        CPC();                                                                 \
    };                                                                         \
    const uint32_t a_fb = (lane & 15) * 144 + (lane >> 4) * 16;                \
    const uint32_t b_fb = 9216 +                                               \
        (wn + (lane & 7) + ((lane >> 4) * 8)) * 144 + ((lane >> 3) & 1) * 16;  \
    uint32_t af[2][4][4], bf[2][2][4];                                         \
    auto ldfrags = [&](int slot, int stg, int ks) {                            \
        const uint32_t ab = s0 + stg * STAGE_BYTES + a_fb + ks * 32;           \
        const uint32_t bb = s0 + stg * STAGE_BYTES + b_fb + ks * 32;           \
        _Pragma("unroll") for (int mi = 0; mi < 4; mi++)                       \
            ldmx4(af[slot][mi], ab + mi * (16 * 144));                         \
        _Pragma("unroll") for (int nj = 0; nj < 2; nj++)                       \
            ldmx4(bf[slot][nj], bb + nj * (16 * 144));                         \
    };                                                                         \
    auto mma_all = [&](int slot) {                                             \
        _Pragma("unroll") for (int mi = 0; mi < 4; mi++)                       \
        _Pragma("unroll") for (int nj = 0; nj < 4; nj++)                       \
            mma16816(acc[mi][nj], af[slot][mi], &bf[slot][nj >> 1][(nj & 1) * 2]); \
    };                                                                         \
    const int niter = (K) / 64;                                                \
    load_stage(0, 0);                                                          \
    load_stage(1, 64);                                                         \
    CPW1();                                                                    \
    __syncthreads();                                                           \
    ldfrags(0, 0, 0);                                                          \
    int st = 0;                                                                \
    for (int it = 0; it < niter; ++it) {                                       \
        ldfrags(1, st, 1); mma_all(0);                                         \
        ldfrags(0, st, 2); mma_all(1);                                         \
        ldfrags(1, st, 3); mma_all(0);                                         \
        if (it + 1 < niter) {                                                  \
            CPW0();                                                            \
            __syncthreads();                                                   \
            if (it + 2 < niter) load_stage(st, (it + 2) * 64);                 \
            ldfrags(0, st ^ 1, 0);                                             \
            st ^= 1;                                                           \
        }                                                                      \
        mma_all(1);                                                            \
    }

// ---------------------------------------------------------------------------
// Generic pipelined GEMM with plain epilogue
// ---------------------------------------------------------------------------
template<bool HALF_OUT, bool BIAS>
__device__ __forceinline__ void gemm_big(
    const __half* __restrict__ A, const __half* __restrict__ B,
    void* __restrict__ Cp, const float* __restrict__ bias,
    int K, int lda, int ldb, int ldc, int m0, int n0)
{
    extern __shared__ char dsm[];
    GEMM_MAINLOOP(A, B, K, lda, ldb, m0, n0)

    const int g  = lane >> 2;
    const int tg = lane & 3;
#pragma unroll
    for (int mi = 0; mi < 4; mi++) {
#pragma unroll
        for (int nj = 0; nj < 4; nj++) {
            const int r0 = m0 + mi * 16 + g;
            const int cc = n0 + wn + nj * 8 + 2 * tg;
            float* a4 = acc[mi][nj];
            if (HALF_OUT) {
                __half* C = (__half*)Cp;
                *(__half2*)&C[(size_t)r0 * ldc + cc]       = __floats2half2_rn(a4[0], a4[1]);
                *(__half2*)&C[(size_t)(r0 + 8) * ldc + cc] = __floats2half2_rn(a4[2], a4[3]);
            } else {
                float* C = (float*)Cp;
                float b0 = 0.f, b1 = 0.f;
                if (BIAS) { float2 bb = *(const float2*)&bias[cc]; b0 = bb.x; b1 = bb.y; }
                *(float2*)&C[(size_t)r0 * ldc + cc]       = make_float2(a4[0] + b0, a4[1] + b1);
                *(float2*)&C[(size_t)(r0 + 8) * ldc + cc] = make_float2(a4[2] + b0, a4[3] + b1);
            }
        }
    }
}

// ---------------------------------------------------------------------------
// k_qkv: qkv[b][m][n] = Wqkv[m,:] . x[b][n,:] with FUSED epilogues:
//  m0<1024 (q,k): channel-major store + per-row sum-of-squares partials
//  m0>=1024 (v) : transpose in smem, store token-major into g_vt
//  grid (64 n-tiles, 24 m-tiles, 4 batches), 128 threads, 3 CTAs/SM.
// ---------------------------------------------------------------------------
__global__ void __launch_bounds__(128, 3) k_qkv()
{
    extern __shared__ char dsm[];
    const int m0 = blockIdx.y * 64;
    const int n0 = blockIdx.x * 128;
    const int b  = blockIdx.z;
    const __half* Bx = g_xh + (size_t)b * Nn * Cn;

    GEMM_MAINLOOP(g_wqh, Bx, 512, 512, 512, m0, n0)

    const int g  = lane >> 2;
    const int tg = lane & 3;

    if (m0 < 1024) {
        __half* C = g_qkv + (size_t)b * 1024 * Nn;
#pragma unroll
        for (int mi = 0; mi < 4; mi++) {
#pragma unroll
            for (int nj = 0; nj < 4; nj++) {
                const int r0 = m0 + mi * 16 + g;
                const int cc = n0 + wn + nj * 8 + 2 * tg;
                float* a4 = acc[mi][nj];
                *(__half2*)&C[(size_t)r0 * Nn + cc]       = __floats2half2_rn(a4[0], a4[1]);
                *(__half2*)&C[(size_t)(r0 + 8) * Nn + cc] = __floats2half2_rn(a4[2], a4[3]);
            }
        }
        float* snorm = (float*)dsm;
        __syncthreads();
        if (tid < 64) snorm[tid] = 0.f;
        __syncthreads();
#pragma unroll
        for (int mi = 0; mi < 4; mi++) {
            float ssA = 0.f, ssB = 0.f;
#pragma unroll
            for (int nj = 0; nj < 4; nj++) {
                float* a4 = acc[mi][nj];
                ssA = fmaf(a4[0], a4[0], fmaf(a4[1], a4[1], ssA));
                ssB = fmaf(a4[2], a4[2], fmaf(a4[3], a4[3], ssB));
            }
            ssA += __shfl_xor_sync(0xffffffffu, ssA, 1);
            ssA += __shfl_xor_sync(0xffffffffu, ssA, 2);
            ssB += __shfl_xor_sync(0xffffffffu, ssB, 1);
            ssB += __shfl_xor_sync(0xffffffffu, ssB, 2);
            if (tg == 0) {
                atomicAdd(&snorm[mi * 16 + g], ssA);
                atomicAdd(&snorm[mi * 16 + g + 8], ssB);
            }
        }
        __syncthreads();
        if (tid < 64)
            g_nP[((size_t)b * 64 + blockIdx.x) * 1024 + m0 + tid] = snorm[tid];
    } else {
        __half* tS = (__half*)dsm;     // [128 n][72 m] halves (144B rows)
        __syncthreads();
#pragma unroll
        for (int mi = 0; mi < 4; mi++) {
#pragma unroll
            for (int nj = 0; nj < 4; nj++) {
                const int ml = mi * 16 + g;
                const int nl = wn + nj * 8 + 2 * tg;
                float* a4 = acc[mi][nj];
                tS[nl * 72 + ml]           = __float2half_rn(a4[0]);
                tS[(nl + 1) * 72 + ml]     = __float2half_rn(a4[1]);
                tS[nl * 72 + ml + 8]       = __float2half_rn(a4[2]);
                tS[(nl + 1) * 72 + ml + 8] = __float2half_rn(a4[3]);
            }
        }
        __syncthreads();
        const int hd0 = m0 - 1024;
        // each thread copies its row (64 halves = 8 uint4)
        const __half* src = tS + tid * 72;
        __half* dst = g_vt + ((size_t)b * Nn + n0 + tid) * Cn + hd0;
#pragma unroll
        for (int k = 0; k < 8; k++)
            ((uint4*)dst)[k] = ((const uint4*)src)[k];
    }
}

// reduce norm partials -> inverse norms
__global__ void __launch_bounds__(256) inv_kernel()
{
    const int idx = blockIdx.x * 256 + threadIdx.x;
    const int b = idx >> 10, m = idx & 1023;
    float s = 0.f;
#pragma unroll 8
    for (int j = 0; j < 64; j++)
        s += g_nP[((size_t)b * 64 + j) * 1024 + m];
    g_inv[b * 1024 + m] = 1.f / fmaxf(sqrtf(s), 1e-12f);
}

// 3. split-K q@k^T partials (fp32 out); grid (splits, 2 m-tiles, 16 bh)
__global__ void __launch_bounds__(128, 3) k_qk()
{
    const int bh = blockIdx.z;
    const __half* qb = g_qkv + ((size_t)(bh >> 2) * 1024 + (bh & 3) * DHn) * Nn
                     + blockIdx.x * 512;
    const __half* kb = qb + (size_t)512 * Nn;
    float* C = g_attnP + ((size_t)bh * QK_SPLIT + blockIdx.x) * (DHn * DHn);
    gemm_big<false, false>(qb, kb, C, nullptr, 512, Nn, Nn, DHn,
                           blockIdx.y * 64, 0);
}

// 4. reduce + scale + softmax; writes TRANSPOSED attn: g_attnT[bh][d][c]
__global__ void __launch_bounds__(128) softmax_kernel(const float* __restrict__ temp)
{
    const int bh = blockIdx.x >> 7;
    const int c  = blockIdx.x & 127;
    const int b  = bh >> 2, h = bh & 3;
    const int d  = threadIdx.x;

    const float* base = g_attnP + (size_t)bh * QK_SPLIT * (DHn * DHn) + c * DHn + d;
    float s = 0.f;
#pragma unroll
    for (int p = 0; p < QK_SPLIT; p++) s += base[(size_t)p * (DHn * DHn)];

    const float qinv = g_inv[b * 1024 + h * DHn + c];
    const float kinv = g_inv[b * 1024 + 512 + h * DHn + d];
    const float val  = s * qinv * kinv * temp[h];

    __shared__ float red[128];
    red[d] = val;
    __syncthreads();
    for (int off = 64; off; off >>= 1) {
        if (d < off) red[d] = fmaxf(red[d], red[d + off]);
        __syncthreads();
    }
    const float mx = red[0];
    __syncthreads();
    const float e = expf(val - mx);
    red[d] = e;
    __syncthreads();
    for (int off = 64; off; off >>= 1) {
        if (d < off) red[d] += red[d + off];
        __syncthreads();
    }
    g_attnT[(size_t)bh * (DHn * DHn) + d * DHn + c] = __float2half_rn(e / red[0]);
}

// 5. M_b[j][h*128+d] = sum_c Wout[j][h*128+c] * attn_bh[c][d]; grid (1,8,16)
__global__ void __launch_bounds__(128, 3) k_M()
{
    const int bh = blockIdx.z;
    const int b = bh >> 2, h = bh & 3;
    const __half* A  = g_woh + h * DHn;
    const __half* Bt = g_attnT + (size_t)bh * DHn * DHn;
    __half* C = g_M + (size_t)b * Cn * Cn + h * DHn;
    gemm_big<true, false>(A, Bt, C, nullptr, DHn, 512, DHn, Cn,
                          blockIdx.y * 64, 0);
}

// 6. out[b] = v_t[b] @ M_b^T + bias; grid (4 j-tiles, 128 n-tiles, 4 b)
__global__ void __launch_bounds__(128, 3) k_out(float* __restrict__ out,
                                                const float* __restrict__ bias)
{
    const int b = blockIdx.z;
    const __half* A = g_vt + (size_t)b * Nn * Cn;
    const __half* Bm = g_M + (size_t)b * Cn * Cn;
    float* C = out + (size_t)b * Nn * Cn;
    gemm_big<false, true>(A, Bm, C, bias, 512, 512, 512, 512,
                          blockIdx.y * 64, blockIdx.x * 128);
}

// ---------------- small kernels ---------------------------------------------
__global__ void __launch_bounds__(256) f2h(const float* __restrict__ s,
                                           __half* __restrict__ d, int n4)
{
    const int i = blockIdx.x * 256 + threadIdx.x;
    if (i < n4) {
        float4 v = ((const float4*)s)[i];
        ((__half2*)d)[i * 2]     = __floats2half2_rn(v.x, v.y);
        ((__half2*)d)[i * 2 + 1] = __floats2half2_rn(v.z, v.w);
    }
}

// ---------------------------------------------------------------------------
extern "C" void kernel_launch(void* const* d_in, const int* in_sizes, int n_in,
                              void* d_out, int out_size)
{
    const float* x    = (const float*)d_in[0];
    const float* Wqkv = (const float*)d_in[1];
    const float* Wout = (const float*)d_in[2];
    const float* bout = (const float*)d_in[3];
    const float* temp = (const float*)d_in[4];
    float* out = (float*)d_out;

    __half *xh, *wqh, *woh;
    cudaGetSymbolAddress((void**)&xh,  g_xh);
    cudaGetSymbolAddress((void**)&wqh, g_wqh);
    cudaGetSymbolAddress((void**)&woh, g_woh);

    cudaFuncSetAttribute(k_qkv, cudaFuncAttributeMaxDynamicSharedMemorySize, BIG_SMEM);
    cudaFuncSetAttribute(k_qk,  cudaFuncAttributeMaxDynamicSharedMemorySize, BIG_SMEM);
    cudaFuncSetAttribute(k_M,   cudaFuncAttributeMaxDynamicSharedMemorySize, BIG_SMEM);
    cudaFuncSetAttribute(k_out, cudaFuncAttributeMaxDynamicSharedMemorySize, BIG_SMEM);

    // 0. fp32 -> fp16 conversions
    f2h<<<(Bn * Nn * Cn / 4 + 255) / 256, 256>>>(x, xh, Bn * Nn * Cn / 4);
    f2h<<<(1536 * 512 / 4 + 255) / 256, 256>>>(Wqkv, wqh, 1536 * 512 / 4);
    f2h<<<(512 * 512 / 4 + 255) / 256, 256>>>(Wout, woh, 512 * 512 / 4);

    // 1. QKV GEMM with fused norm partials + v transpose
    k_qkv<<<dim3(64, 24, 4), 128, BIG_SMEM>>>();

    // 2. inverse L2 norms
    inv_kernel<<<16, 256>>>();

    // 3. split-K q@k^T partials
    k_qk<<<dim3(QK_SPLIT, 2, 16), 128, BIG_SMEM>>>();

    // 4. reduce + scale + softmax (transposed output)
    softmax_kernel<<<16 * 128, 128>>>(temp);

    // 5. M = Wout_h @ attn_h  (tiny fused GEMM)
    k_M<<<dim3(1, 8, 16), 128, BIG_SMEM>>>();

    // 6. out = v_t @ M^T + bias
    k_out<<<dim3(4, 128, 4), 128, BIG_SMEM>>>(out, bout);
}

// round 12
// speedup vs baseline: 1.3580x; 1.3580x over previous
#include <cuda_runtime.h>
#include <cuda_fp16.h>
#include <cstddef>
#include <cstdint>

#define Bn   4
#define Nn   8192
#define Cn   512
#define DHn  128
#define GSPL 8                      // gram split-K chunks (1024 tokens each)

// ---------------- scratch (device globals) ---------------------------------
__device__ __align__(128) __half g_xh  [(size_t)Bn * Nn * Cn];   // x token-major (33MB)
__device__ __align__(128) __half g_xt  [(size_t)Bn * Cn * Nn];   // x channel-major (33MB)
__device__ __align__(128) __half g_wqk2[1024 * 1024];            // [Wqk | Wqk] dup cols
__device__ __align__(128) __half g_woh [512 * 512];
__device__ __align__(128) __half g_wvt [512 * 512];              // Wv^T
__device__ __align__(128) float  g_gramP[(size_t)Bn * GSPL * 512 * 512]; // 32MB
__device__ __align__(128) __half g_g2  [Bn * 512 * 1024];        // [G_hi | G_lo] rows
__device__ __align__(128) __half g_T1  [Bn * 1024 * 512];        // Wqk @ G
__device__ __align__(128) float  g_qk3 [3 * 16 * DHn * DHn];     // QK, QQ, KK
__device__ __align__(128) __half g_attnT[16 * DHn * DHn];        // [bh][d][c]
__device__ __align__(128) __half g_M   [Bn * Cn * Cn];           // Wout_h @ attn_h
__device__ __align__(128) __half g_P   [Bn * Cn * Cn];           // M @ Wv

// ---------------- PTX helpers ----------------------------------------------
__device__ __forceinline__ uint32_t sptr(const void* p) {
    return (uint32_t)__cvta_generic_to_shared(p);
}
#define CPA(dst, src) asm volatile("cp.async.cg.shared.global [%0],[%1],16;\n" \
                                   :: "r"(dst), "l"(src))
#define CPC() asm volatile("cp.async.commit_group;\n")
#define CPW0() asm volatile("cp.async.wait_group 0;\n")
#define CPW1() asm volatile("cp.async.wait_group 1;\n")

__device__ __forceinline__ void ldmx4(uint32_t* r, uint32_t a) {
    asm volatile("ldmatrix.sync.aligned.m8n8.x4.shared.b16 {%0,%1,%2,%3},[%4];"
                 : "=r"(r[0]), "=r"(r[1]), "=r"(r[2]), "=r"(r[3]) : "r"(a));
}
__device__ __forceinline__ void mma16816(float* c, const uint32_t* a, const uint32_t* b) {
    asm volatile(
        "mma.sync.aligned.m16n8k16.row.col.f32.f16.f16.f32 "
        "{%0,%1,%2,%3},{%4,%5,%6,%7},{%8,%9},{%0,%1,%2,%3};"
        : "+f"(c[0]), "+f"(c[1]), "+f"(c[2]), "+f"(c[3])
        : "r"(a[0]), "r"(a[1]), "r"(a[2]), "r"(a[3]), "r"(b[0]), "r"(b[1]));
}

// ---------------------------------------------------------------------------
// Pipelined 128x128 GEMM mainloop (R10 config): BK=64, 2-stage ring, one
// barrier per iter, 128 threads = 4 warps of 64x64. 2 CTAs/SM.
// Stage: A 128 rows x 144B at +0, B at +18432. K%64==0, K/64>=2.
// ---------------------------------------------------------------------------
#define STAGE_BYTES 36864
#define BIG_SMEM    (2 * STAGE_BYTES)   // 73728

#define GEMM_MAINLOOP(A, B, K, lda, ldb, m0, n0)                               \
    const uint32_t s0 = sptr(dsm);                                             \
    const int tid  = threadIdx.x;                                              \
    const int lane = tid & 31;                                                 \
    const int wid  = tid >> 5;                                                 \
    const int wm   = (wid & 1) * 64;                                           \
    const int wn   = (wid >> 1) * 64;                                          \
    float acc[4][8][4];                                                        \
    _Pragma("unroll") for (int i = 0; i < 4; i++)                              \
    _Pragma("unroll") for (int j = 0; j < 8; j++)                              \
    _Pragma("unroll") for (int t = 0; t < 4; t++) acc[i][j][t] = 0.f;          \
    const int lrow = tid >> 3;           /* 0..15 */                           \
    const int lc16 = tid & 7;                                                  \
    const __half* Ag = (A) + (size_t)((m0) + lrow) * (lda) + lc16 * 8;         \
    const __half* Bg = (B) + (size_t)((n0) + lrow) * (ldb) + lc16 * 8;         \
    auto load_stage = [&](int stg, int k0) {                                   \
        const uint32_t ad = s0 + stg * STAGE_BYTES + lrow * 144 + lc16 * 16;   \
        const uint32_t bd = ad + 18432;                                        \
        _Pragma("unroll") for (int u = 0; u < 8; u++) {                        \
            CPA(ad + u * (16 * 144), Ag + (size_t)(u * 16) * (lda) + k0);      \
            CPA(bd + u * (16 * 144), Bg + (size_t)(u * 16) * (ldb) + k0);      \
        }                                                                      \
        CPC();                                                                 \
    };                                                                         \
    const uint32_t a_fb = (wm + (lane & 15)) * 144 + (lane >> 4) * 16;         \
    const uint32_t b_fb = 18432 +                                              \
        (wn + (lane & 7) + ((lane >> 4) * 8)) * 144 + ((lane >> 3) & 1) * 16;  \
    uint32_t af[2][4][4], bf[2][4][4];                                         \
    auto ldfrags = [&](int slot, int stg, int ks) {                            \
        const uint32_t ab = s0 + stg * STAGE_BYTES + a_fb + ks * 32;           \
        const uint32_t bb = s0 + stg * STAGE_BYTES + b_fb + ks * 32;           \
        _Pragma("unroll") for (int mi = 0; mi < 4; mi++)                       \
            ldmx4(af[slot][mi], ab + mi * (16 * 144));                         \
        _Pragma("unroll") for (int nj = 0; nj < 4; nj++)                       \
            ldmx4(bf[slot][nj], bb + nj * (16 * 144));                         \
    };                                                                         \
    auto mma_all = [&](int slot) {                                             \
        _Pragma("unroll") for (int mi = 0; mi < 4; mi++)                       \
        _Pragma("unroll") for (int nj = 0; nj < 8; nj++)                       \
            mma16816(acc[mi][nj], af[slot][mi], &bf[slot][nj >> 1][(nj & 1) * 2]); \
    };                                                                         \
    const int niter = (K) / 64;                                                \
    load_stage(0, 0);                                                          \
    load_stage(1, 64);                                                         \
    CPW1();                                                                    \
    __syncthreads();                                                           \
    ldfrags(0, 0, 0);                                                          \
    int st = 0;                                                                \
    for (int it = 0; it < niter; ++it) {                                       \
        ldfrags(1, st, 1); mma_all(0);                                         \
        ldfrags(0, st, 2); mma_all(1);                                         \
        ldfrags(1, st, 3); mma_all(0);                                         \
        if (it + 1 < niter) {                                                  \
            CPW0();                                                            \
            __syncthreads();                                                   \
            if (it + 2 < niter) load_stage(st, (it + 2) * 64);                 \
            ldfrags(0, st ^ 1, 0);                                             \
            st ^= 1;                                                           \
        }                                                                      \
        mma_all(1);                                                            \
    }

template<bool HALF_OUT, bool BIAS>
__device__ __forceinline__ void gemm_big(
    const __half* __restrict__ A, const __half* __restrict__ B,
    void* __restrict__ Cp, const float* __restrict__ bias,
    int K, int lda, int ldb, int ldc, int m0, int n0)
{
    extern __shared__ char dsm[];
    GEMM_MAINLOOP(A, B, K, lda, ldb, m0, n0)

    const int g  = lane >> 2;
    const int tg = lane & 3;
#pragma unroll
    for (int mi = 0; mi < 4; mi++) {
#pragma unroll
        for (int nj = 0; nj < 8; nj++) {
            const int r0 = m0 + wm + mi * 16 + g;
            const int cc = n0 + wn + nj * 8 + 2 * tg;
            float* a4 = acc[mi][nj];
            if (HALF_OUT) {
                __half* C = (__half*)Cp;
                *(__half2*)&C[(size_t)r0 * ldc + cc]       = __floats2half2_rn(a4[0], a4[1]);
                *(__half2*)&C[(size_t)(r0 + 8) * ldc + cc] = __floats2half2_rn(a4[2], a4[3]);
            } else {
                float* C = (float*)Cp;
                float b0 = 0.f, b1 = 0.f;
                if (BIAS) { float2 bb = *(const float2*)&bias[cc]; b0 = bb.x; b1 = bb.y; }
                *(float2*)&C[(size_t)r0 * ldc + cc]       = make_float2(a4[0] + b0, a4[1] + b1);
                *(float2*)&C[(size_t)(r0 + 8) * ldc + cc] = make_float2(a4[2] + b0, a4[3] + b1);
            }
        }
    }
}

// ---------------- GEMM kernel wrappers --------------------------------------
// 1. Gram partials: G_b[i][j] = sum_n xt[i][n] xt[j][n], split-K over tokens.
//    grid (GSPL splits, 16 tiles, 4 batches)
__global__ void __launch_bounds__(128, 2) k_gram()
{
    const int b = blockIdx.z;
    const int m0 = (blockIdx.y >> 2) * 128;
    const int n0 = (blockIdx.y & 3) * 128;
    const __half* X = g_xt + (size_t)b * Cn * Nn + (size_t)blockIdx.x * (Nn / GSPL);
    float* C = g_gramP + ((size_t)b * GSPL + blockIdx.x) * (512 * 512);
    gemm_big<false, false>(X, X, C, nullptr, Nn / GSPL, Nn, Nn, 512, m0, n0);
}

// 2. T1 = Wqk @ G  (hi+lo via duplicated-K operands), half out
//    grid (4 n-tiles, 8 m-tiles, 4 batches)
__global__ void __launch_bounds__(128, 2) k_T1()
{
    const int b = blockIdx.z;
    const __half* Bg = g_g2 + (size_t)b * 512 * 1024;
    __half* C = g_T1 + (size_t)b * 1024 * 512;
    gemm_big<true, false>(g_wqk2, Bg, C, nullptr, 1024, 1024, 1024, 512,
                          blockIdx.y * 128, blockIdx.x * 128);
}

// 3. QK / QQ / KK products per bh: grid (3 products, 1, 16 bh)
__global__ void __launch_bounds__(128, 2) k_qk3()
{
    const int prod = blockIdx.x;
    const int bh = blockIdx.z;
    const int b = bh >> 2, h = bh & 3;
    const __half* T1b = g_T1 + (size_t)b * 1024 * 512;
    const __half* A  = T1b + (size_t)((prod == 2 ? 512 : 0) + h * DHn) * 512;
    const __half* Bp = g_wqk2 + (size_t)((prod == 1 ? 0 : 512) + h * DHn) * 1024;
    float* C = g_qk3 + ((size_t)prod * 16 + bh) * (DHn * DHn);
    gemm_big<false, false>(A, Bp, C, nullptr, 512, 512, 1024, DHn, 0, 0);
}

// 4. softmax over d with fused normalization; writes attnT[bh][d][c]
__global__ void __launch_bounds__(128) softmax_kernel(const float* __restrict__ temp)
{
    const int bh = blockIdx.x >> 7;
    const int c  = blockIdx.x & 127;
    const int h  = bh & 3;
    const int d  = threadIdx.x;

    const float s  = g_qk3[((size_t)0 * 16 + bh) * (DHn * DHn) + c * DHn + d];
    const float qq = g_qk3[((size_t)1 * 16 + bh) * (DHn * DHn) + c * DHn + c];
    const float kk = g_qk3[((size_t)2 * 16 + bh) * (DHn * DHn) + d * DHn + d];
    const float qinv = 1.f / fmaxf(sqrtf(fmaxf(qq, 0.f)), 1e-12f);
    const float kinv = 1.f / fmaxf(sqrtf(fmaxf(kk, 0.f)), 1e-12f);
    const float val  = s * qinv * kinv * temp[h];

    __shared__ float red[128];
    red[d] = val;
    __syncthreads();
    for (int off = 64; off; off >>= 1) {
        if (d < off) red[d] = fmaxf(red[d], red[d + off]);
        __syncthreads();
    }
    const float mx = red[0];
    __syncthreads();
    const float e = expf(val - mx);
    red[d] = e;
    __syncthreads();
    for (int off = 64; off; off >>= 1) {
        if (d < off) red[d] += red[d + off];
        __syncthreads();
    }
    g_attnT[(size_t)bh * (DHn * DHn) + d * DHn + c] = __float2half_rn(e / red[0]);
}

// 5. M_b[j][h*128+d] = Wout_h @ attn_bh   grid (1, 4, 16)
__global__ void __launch_bounds__(128, 2) k_M()
{
    const int bh = blockIdx.z;
    const int b = bh >> 2, h = bh & 3;
    const __half* A  = g_woh + h * DHn;
    const __half* Bt = g_attnT + (size_t)bh * DHn * DHn;
    __half* C = g_M + (size_t)b * Cn * Cn + h * DHn;
    gemm_big<true, false>(A, Bt, C, nullptr, DHn, 512, DHn, Cn,
                          blockIdx.y * 128, 0);
}

// 6. P_b = M_b @ Wv  (B = Wv^T rows), half out. grid (4, 4, 4)
__global__ void __launch_bounds__(128, 2) k_P()
{
    const int b = blockIdx.z;
    const __half* A = g_M + (size_t)b * Cn * Cn;
    __half* C = g_P + (size_t)b * Cn * Cn;
    gemm_big<true, false>(A, g_wvt, C, nullptr, 512, 512, 512, 512,
                          blockIdx.y * 128, blockIdx.x * 128);
}

// 7. out = x @ P^T + bias   grid (4 j-tiles, 64 n-tiles, 4 batches)
__global__ void __launch_bounds__(128, 2) k_out(float* __restrict__ out,
                                                const float* __restrict__ bias)
{
    const int b = blockIdx.z;
    const __half* A = g_xh + (size_t)b * Nn * Cn;
    const __half* Bp = g_P + (size_t)b * Cn * Cn;
    float* C = out + (size_t)b * Nn * Cn;
    gemm_big<false, true>(A, Bp, C, bias, 512, 512, 512, 512,
                          blockIdx.y * 128, blockIdx.x * 128);
}

// ---------------- small kernels ---------------------------------------------
__global__ void __launch_bounds__(256) f2h(const float* __restrict__ s,
                                           __half* __restrict__ d, int n4)
{
    const int i = blockIdx.x * 256 + threadIdx.x;
    if (i < n4) {
        float4 v = ((const float4*)s)[i];
        ((__half2*)d)[i * 2]     = __floats2half2_rn(v.x, v.y);
        ((__half2*)d)[i * 2 + 1] = __floats2half2_rn(v.z, v.w);
    }
}

// x [b][n][c] fp32 -> g_xt [b][c][n] fp16
__global__ void __launch_bounds__(256) xtrans(const float* __restrict__ x)
{
    __shared__ __half ts[32][33];
    const int n0 = blockIdx.x * 32, c0 = blockIdx.y * 32, b = blockIdx.z;
    const int tx = threadIdx.x, ty = threadIdx.y;
#pragma unroll
    for (int r = 0; r < 4; r++)
        ts[ty + r * 8][tx] = __float2half_rn(
            x[((size_t)b * Nn + n0 + ty + r * 8) * Cn + c0 + tx]);
    __syncthreads();
#pragma unroll
    for (int r = 0; r < 4; r++)
        g_xt[((size_t)b * Cn + c0 + ty + r * 8) * Nn + n0 + tx] = ts[tx][ty + r * 8];
}

// weights prep: wqk2 (dup cols), woh, wvt (= Wv^T)
__global__ void __launch_bounds__(256) wprep(const float* __restrict__ Wqkv,
                                             const float* __restrict__ Wout)
{
    const int idx = blockIdx.x * 256 + threadIdx.x;
    if (idx < 1024 * 1024) {
        const int m = idx >> 10, k = idx & 1023;
        g_wqk2[idx] = __float2half_rn(Wqkv[m * 512 + (k & 511)]);
    } else if (idx < 1024 * 1024 + 262144) {
        const int t = idx - 1024 * 1024;
        g_woh[t] = __float2half_rn(Wout[t]);
    } else {
        const int t = idx - 1024 * 1024 - 262144;
        const int j = t >> 9, m = t & 511;
        g_wvt[t] = __float2half_rn(Wqkv[(1024 + m) * 512 + j]);
    }
}

// reduce gram partials -> fp32 -> hi/lo fp16 pair in g_g2
__global__ void __launch_bounds__(256) gred()
{
    const int idx = blockIdx.x * 256 + threadIdx.x;   // 0 .. 4*262144-1
    const int b  = idx >> 18;
    const int ij = idx & 262143;
    float s = 0.f;
#pragma unroll
    for (int p = 0; p < GSPL; p++)
        s += g_gramP[((size_t)b * GSPL + p) * 262144 + ij];
    const __half hi = __float2half_rn(s);
    const float  lo = s - __half2float(hi);
    const int i = ij >> 9, j = ij & 511;
    g_g2[((size_t)b * 512 + i) * 1024 + j]       = hi;
    g_g2[((size_t)b * 512 + i) * 1024 + 512 + j] = __float2half_rn(lo);
}

// ---------------------------------------------------------------------------
extern "C" void kernel_launch(void* const* d_in, const int* in_sizes, int n_in,
                              void* d_out, int out_size)
{
    const float* x    = (const float*)d_in[0];
    const float* Wqkv = (const float*)d_in[1];
    const float* Wout = (const float*)d_in[2];
    const float* bout = (const float*)d_in[3];
    const float* temp = (const float*)d_in[4];
    float* out = (float*)d_out;

    __half* xh;
    cudaGetSymbolAddress((void**)&xh, g_xh);

    cudaFuncSetAttribute(k_gram, cudaFuncAttributeMaxDynamicSharedMemorySize, BIG_SMEM);
    cudaFuncSetAttribute(k_T1,   cudaFuncAttributeMaxDynamicSharedMemorySize, BIG_SMEM);
    cudaFuncSetAttribute(k_qk3,  cudaFuncAttributeMaxDynamicSharedMemorySize, BIG_SMEM);
    cudaFuncSetAttribute(k_M,    cudaFuncAttributeMaxDynamicSharedMemorySize, BIG_SMEM);
    cudaFuncSetAttribute(k_P,    cudaFuncAttributeMaxDynamicSharedMemorySize, BIG_SMEM);
    cudaFuncSetAttribute(k_out,  cudaFuncAttributeMaxDynamicSharedMemorySize, BIG_SMEM);

    // 0. conversions / layouts
    f2h<<<(Bn * Nn * Cn / 4 + 255) / 256, 256>>>(x, xh, Bn * Nn * Cn / 4);
    xtrans<<<dim3(Nn / 32, Cn / 32, Bn), dim3(32, 8)>>>(x);
    wprep<<<6144, 256>>>(Wqkv, Wout);

    // 1. Gram partials + reduce/split
    k_gram<<<dim3(GSPL, 16, Bn), 128, BIG_SMEM>>>();
    gred<<<(Bn * 262144) / 256, 256>>>();

    // 2. T1 = Wqk @ G (hi+lo)
    k_T1<<<dim3(4, 8, Bn), 128, BIG_SMEM>>>();

    // 3. QK / QQ / KK
    k_qk3<<<dim3(3, 1, 16), 128, BIG_SMEM>>>();

    // 4. softmax (normalization fused)
    softmax_kernel<<<16 * 128, 128>>>(temp);

    // 5. M = Wout_h @ attn_h
    k_M<<<dim3(1, 4, 16), 128, BIG_SMEM>>>();

    // 6. P = M @ Wv
    k_P<<<dim3(4, 4, Bn), 128, BIG_SMEM>>>();

    // 7. out = x @ P^T + bias
    k_out<<<dim3(4, 64, Bn), 128, BIG_SMEM>>>(out, bout);
}

// round 13
// speedup vs baseline: 1.4320x; 1.0545x over previous
#include <cuda_runtime.h>
#include <cuda_fp16.h>
#include <cstddef>
#include <cstdint>

#define Bn   4
#define Nn   8192
#define Cn   512
#define DHn  128
#define GSPL 8                      // gram split-K chunks (1024 tokens each)

// ---------------- scratch (device globals) ---------------------------------
__device__ __align__(128) __half g_xh  [(size_t)Bn * Nn * Cn];   // x token-major
__device__ __align__(128) __half g_xt  [(size_t)Bn * Cn * Nn];   // x channel-major
__device__ __align__(128) __half g_wqk2[1024 * 1024];            // [Wqk | Wqk] dup cols
__device__ __align__(128) __half g_woh [512 * 512];
__device__ __align__(128) __half g_wvt [512 * 512];              // Wv^T
__device__ __align__(128) float  g_gramP[(size_t)Bn * GSPL * 512 * 512];
__device__ __align__(128) __half g_g2  [Bn * 512 * 1024];        // [G_hi | G_lo] rows
__device__ __align__(128) __half g_T1  [Bn * 1024 * 512];        // Wqk @ G
__device__ __align__(128) float  g_qk  [16 * DHn * DHn];         // QK logits
__device__ __align__(128) float  g_diag[Bn * 1024];              // qq (0-511), kk (512-1023)
__device__ __align__(128) __half g_attnT[16 * DHn * DHn];        // [bh][d][c]
__device__ __align__(128) __half g_M   [Bn * Cn * Cn];           // Wout_h @ attn_h
__device__ __align__(128) __half g_P   [Bn * Cn * Cn];           // M @ Wv

// upper-triangle tile map (4x4 -> 10 tiles)
__device__ const int c_ti[10] = {0,0,0,0,1,1,1,2,2,3};
__device__ const int c_tj[10] = {0,1,2,3,1,2,3,2,3,3};

// ---------------- PTX helpers ----------------------------------------------
__device__ __forceinline__ uint32_t sptr(const void* p) {
    return (uint32_t)__cvta_generic_to_shared(p);
}
#define CPA(dst, src) asm volatile("cp.async.cg.shared.global [%0],[%1],16;\n" \
                                   :: "r"(dst), "l"(src))
#define CPC() asm volatile("cp.async.commit_group;\n")
#define CPW0() asm volatile("cp.async.wait_group 0;\n")
#define CPW1() asm volatile("cp.async.wait_group 1;\n")

__device__ __forceinline__ void ldmx4(uint32_t* r, uint32_t a) {
    asm volatile("ldmatrix.sync.aligned.m8n8.x4.shared.b16 {%0,%1,%2,%3},[%4];"
                 : "=r"(r[0]), "=r"(r[1]), "=r"(r[2]), "=r"(r[3]) : "r"(a));
}
__device__ __forceinline__ void mma16816(float* c, const uint32_t* a, const uint32_t* b) {
    asm volatile(
        "mma.sync.aligned.m16n8k16.row.col.f32.f16.f16.f32 "
        "{%0,%1,%2,%3},{%4,%5,%6,%7},{%8,%9},{%0,%1,%2,%3};"
        : "+f"(c[0]), "+f"(c[1]), "+f"(c[2]), "+f"(c[3])
        : "r"(a[0]), "r"(a[1]), "r"(a[2]), "r"(a[3]), "r"(b[0]), "r"(b[1]));
}

// ---------------------------------------------------------------------------
// Pipelined 128x128 GEMM mainloop (R10 config): BK=64, 2-stage ring, one
// barrier per iter, 128 threads = 4 warps of 64x64. 2 CTAs/SM.
// ---------------------------------------------------------------------------
#define STAGE_BYTES 36864
#define BIG_SMEM    (2 * STAGE_BYTES)   // 73728

#define GEMM_MAINLOOP(A, B, K, lda, ldb, m0, n0)                               \
    const uint32_t s0 = sptr(dsm);                                             \
    const int tid  = threadIdx.x;                                              \
    const int lane = tid & 31;                                                 \
    const int wid  = tid >> 5;                                                 \
    const int wm   = (wid & 1) * 64;                                           \
    const int wn   = (wid >> 1) * 64;                                          \
    float acc[4][8][4];                                                        \
    _Pragma("unroll") for (int i = 0; i < 4; i++)                              \
    _Pragma("unroll") for (int j = 0; j < 8; j++)                              \
    _Pragma("unroll") for (int t = 0; t < 4; t++) acc[i][j][t] = 0.f;          \
    const int lrow = tid >> 3;           /* 0..15 */                           \
    const int lc16 = tid & 7;                                                  \
    const __half* Ag = (A) + (size_t)((m0) + lrow) * (lda) + lc16 * 8;         \
    const __half* Bg = (B) + (size_t)((n0) + lrow) * (ldb) + lc16 * 8;         \
    auto load_stage = [&](int stg, int k0) {                                   \
        const uint32_t ad = s0 + stg * STAGE_BYTES + lrow * 144 + lc16 * 16;   \
        const uint32_t bd = ad + 18432;                                        \
        _Pragma("unroll") for (int u = 0; u < 8; u++) {                        \
            CPA(ad + u * (16 * 144), Ag + (size_t)(u * 16) * (lda) + k0);      \
            CPA(bd + u * (16 * 144), Bg + (size_t)(u * 16) * (ldb) + k0);      \
        }                                                                      \
        CPC();                                                                 \
    };                                                                         \
    const uint32_t a_fb = (wm + (lane & 15)) * 144 + (lane >> 4) * 16;         \
    const uint32_t b_fb = 18432 +                                              \
        (wn + (lane & 7) + ((lane >> 4) * 8)) * 144 + ((lane >> 3) & 1) * 16;  \
    uint32_t af[2][4][4], bf[2][4][4];                                         \
    auto ldfrags = [&](int slot, int stg, int ks) {                            \
        const uint32_t ab = s0 + stg * STAGE_BYTES + a_fb + ks * 32;           \
        const uint32_t bb = s0 + stg * STAGE_BYTES + b_fb + ks * 32;           \
        _Pragma("unroll") for (int mi = 0; mi < 4; mi++)                       \
            ldmx4(af[slot][mi], ab + mi * (16 * 144));                         \
        _Pragma("unroll") for (int nj = 0; nj < 4; nj++)                       \
            ldmx4(bf[slot][nj], bb + nj * (16 * 144));                         \
    };                                                                         \
    auto mma_all = [&](int slot) {                                             \
        _Pragma("unroll") for (int mi = 0; mi < 4; mi++)                       \
        _Pragma("unroll") for (int nj = 0; nj < 8; nj++)                       \
            mma16816(acc[mi][nj], af[slot][mi], &bf[slot][nj >> 1][(nj & 1) * 2]); \
    };                                                                         \
    const int niter = (K) / 64;                                                \
    load_stage(0, 0);                                                          \
    load_stage(1, 64);                                                         \
    CPW1();                                                                    \
    __syncthreads();                                                           \
    ldfrags(0, 0, 0);                                                          \
    int st = 0;                                                                \
    for (int it = 0; it < niter; ++it) {                                       \
        ldfrags(1, st, 1); mma_all(0);                                         \
        ldfrags(0, st, 2); mma_all(1);                                         \
        ldfrags(1, st, 3); mma_all(0);                                         \
        if (it + 1 < niter) {                                                  \
            CPW0();                                                            \
            __syncthreads();                                                   \
            if (it + 2 < niter) load_stage(st, (it + 2) * 64);                 \
            ldfrags(0, st ^ 1, 0);                                             \
            st ^= 1;                                                           \
        }                                                                      \
        mma_all(1);                                                            \
    }

template<bool HALF_OUT, bool BIAS>
__device__ __forceinline__ void gemm_big(
    const __half* __restrict__ A, const __half* __restrict__ B,
    void* __restrict__ Cp, const float* __restrict__ bias,
    int K, int lda, int ldb, int ldc, int m0, int n0)
{
    extern __shared__ char dsm[];
    GEMM_MAINLOOP(A, B, K, lda, ldb, m0, n0)

    const int g  = lane >> 2;
    const int tg = lane & 3;
#pragma unroll
    for (int mi = 0; mi < 4; mi++) {
#pragma unroll
        for (int nj = 0; nj < 8; nj++) {
            const int r0 = m0 + wm + mi * 16 + g;
            const int cc = n0 + wn + nj * 8 + 2 * tg;
            float* a4 = acc[mi][nj];
            if (HALF_OUT) {
                __half* C = (__half*)Cp;
                *(__half2*)&C[(size_t)r0 * ldc + cc]       = __floats2half2_rn(a4[0], a4[1]);
                *(__half2*)&C[(size_t)(r0 + 8) * ldc + cc] = __floats2half2_rn(a4[2], a4[3]);
            } else {
                float* C = (float*)Cp;
                float b0 = 0.f, b1 = 0.f;
                if (BIAS) { float2 bb = *(const float2*)&bias[cc]; b0 = bb.x; b1 = bb.y; }
                *(float2*)&C[(size_t)r0 * ldc + cc]       = make_float2(a4[0] + b0, a4[1] + b1);
                *(float2*)&C[(size_t)(r0 + 8) * ldc + cc] = make_float2(a4[2] + b0, a4[3] + b1);
            }
        }
    }
}

// ---------------- GEMM kernel wrappers --------------------------------------
// 1. Gram partials (upper-triangle tiles only): grid (GSPL, 10, 4)
__global__ void __launch_bounds__(128, 2) k_gram()
{
    const int b = blockIdx.z;
    const int m0 = c_ti[blockIdx.y] * 128;
    const int n0 = c_tj[blockIdx.y] * 128;
    const __half* X = g_xt + (size_t)b * Cn * Nn + (size_t)blockIdx.x * (Nn / GSPL);
    float* C = g_gramP + ((size_t)b * GSPL + blockIdx.x) * (512 * 512);
    gemm_big<false, false>(X, X, C, nullptr, Nn / GSPL, Nn, Nn, 512, m0, n0);
}

// 2. T1 = Wqk @ G  (hi+lo via duplicated-K operands), half out
__global__ void __launch_bounds__(128, 2) k_T1()
{
    const int b = blockIdx.z;
    const __half* Bg = g_g2 + (size_t)b * 512 * 1024;
    __half* C = g_T1 + (size_t)b * 1024 * 512;
    gemm_big<true, false>(g_wqk2, Bg, C, nullptr, 1024, 1024, 1024, 512,
                          blockIdx.y * 128, blockIdx.x * 128);
}

// 3. QK logits per bh: grid 16
__global__ void __launch_bounds__(128, 2) k_qkp()
{
    const int bh = blockIdx.x;
    const int b = bh >> 2, h = bh & 3;
    const __half* A  = g_T1 + (size_t)b * 1024 * 512 + (size_t)(h * DHn) * 512;
    const __half* Bp = g_wqk2 + (size_t)(512 + h * DHn) * 1024;
    float* C = g_qk + (size_t)bh * (DHn * DHn);
    gemm_big<false, false>(A, Bp, C, nullptr, 512, 512, 1024, DHn, 0, 0);
}

// 3b. diag dots: g_diag[b*1024+r] = dot(T1[b] row r, Wqk row r)  (warp per row)
__global__ void __launch_bounds__(256) kdiag()
{
    const int gw = blockIdx.x * 8 + (threadIdx.x >> 5);   // 0..4095
    const int b = gw >> 10, r = gw & 1023;
    const int lane = threadIdx.x & 31;
    const __half2* t1 = (const __half2*)(g_T1 + ((size_t)b * 1024 + r) * 512);
    const __half2* wr = (const __half2*)(g_wqk2 + (size_t)r * 1024);
    float s = 0.f;
#pragma unroll
    for (int k = lane; k < 256; k += 32) {
        float2 a = __half22float2(t1[k]);
        float2 w = __half22float2(wr[k]);
        s = fmaf(a.x, w.x, fmaf(a.y, w.y, s));
    }
#pragma unroll
    for (int off = 16; off; off >>= 1)
        s += __shfl_xor_sync(0xffffffffu, s, off);
    if (lane == 0) g_diag[gw] = s;
}

// 4. softmax over d with fused normalization; writes attnT[bh][d][c]
__global__ void __launch_bounds__(128) softmax_kernel(const float* __restrict__ temp)
{
    const int bh = blockIdx.x >> 7;
    const int c  = blockIdx.x & 127;
    const int b  = bh >> 2, h = bh & 3;
    const int d  = threadIdx.x;

    const float s  = g_qk[(size_t)bh * (DHn * DHn) + c * DHn + d];
    const float qq = g_diag[b * 1024 + h * DHn + c];
    const float kk = g_diag[b * 1024 + 512 + h * DHn + d];
    const float qinv = 1.f / fmaxf(sqrtf(fmaxf(qq, 0.f)), 1e-12f);
    const float kinv = 1.f / fmaxf(sqrtf(fmaxf(kk, 0.f)), 1e-12f);
    const float val  = s * qinv * kinv * temp[h];

    __shared__ float red[128];
    red[d] = val;
    __syncthreads();
    for (int off = 64; off; off >>= 1) {
        if (d < off) red[d] = fmaxf(red[d], red[d + off]);
        __syncthreads();
    }
    const float mx = red[0];
    __syncthreads();
    const float e = expf(val - mx);
    red[d] = e;
    __syncthreads();
    for (int off = 64; off; off >>= 1) {
        if (d < off) red[d] += red[d + off];
        __syncthreads();
    }
    g_attnT[(size_t)bh * (DHn * DHn) + d * DHn + c] = __float2half_rn(e / red[0]);
}

// 5. M_b[j][h*128+d] = Wout_h @ attn_bh   grid (1, 4, 16)
__global__ void __launch_bounds__(128, 2) k_M()
{
    const int bh = blockIdx.z;
    const int b = bh >> 2, h = bh & 3;
    const __half* A  = g_woh + h * DHn;
    const __half* Bt = g_attnT + (size_t)bh * DHn * DHn;
    __half* C = g_M + (size_t)b * Cn * Cn + h * DHn;
    gemm_big<true, false>(A, Bt, C, nullptr, DHn, 512, DHn, Cn,
                          blockIdx.y * 128, 0);
}

// 6. P_b = M_b @ Wv, half out. grid (4, 4, 4)
__global__ void __launch_bounds__(128, 2) k_P()
{
    const int b = blockIdx.z;
    const __half* A = g_M + (size_t)b * Cn * Cn;
    __half* C = g_P + (size_t)b * Cn * Cn;
    gemm_big<true, false>(A, g_wvt, C, nullptr, 512, 512, 512, 512,
                          blockIdx.y * 128, blockIdx.x * 128);
}

// 7. out = x @ P^T + bias   grid (4 j-tiles, 64 n-tiles, 4 batches)
__global__ void __launch_bounds__(128, 2) k_out(float* __restrict__ out,
                                                const float* __restrict__ bias)
{
    const int b = blockIdx.z;
    const __half* A = g_xh + (size_t)b * Nn * Cn;
    const __half* Bp = g_P + (size_t)b * Cn * Cn;
    float* C = out + (size_t)b * Nn * Cn;
    gemm_big<false, true>(A, Bp, C, bias, 512, 512, 512, 512,
                          blockIdx.y * 128, blockIdx.x * 128);
}

// ---------------- small kernels ---------------------------------------------
// x [b][n][c] fp32 -> g_xh [b][n][c] fp16 AND g_xt [b][c][n] fp16 (read once)
__global__ void __launch_bounds__(256) xprep(const float* __restrict__ x)
{
    __shared__ __half ts[32][33];
    const int n0 = blockIdx.x * 32, c0 = blockIdx.y * 32, b = blockIdx.z;
    const int tx = threadIdx.x, ty = threadIdx.y;
#pragma unroll
    for (int r = 0; r < 4; r++) {
        const size_t idx = ((size_t)b * Nn + n0 + ty + r * 8) * Cn + c0 + tx;
        const __half hv = __float2half_rn(x[idx]);
        g_xh[idx] = hv;
        ts[ty + r * 8][tx] = hv;
    }
    __syncthreads();
#pragma unroll
    for (int r = 0; r < 4; r++)
        g_xt[((size_t)b * Cn + c0 + ty + r * 8) * Nn + n0 + tx] = ts[tx][ty + r * 8];
}

// weights prep: wqk2 (dup cols), woh, wvt (= Wv^T)
__global__ void __launch_bounds__(256) wprep(const float* __restrict__ Wqkv,
                                             const float* __restrict__ Wout)
{
    const int idx = blockIdx.x * 256 + threadIdx.x;
    if (idx < 1024 * 1024) {
        const int m = idx >> 10, k = idx & 1023;
        g_wqk2[idx] = __float2half_rn(Wqkv[m * 512 + (k & 511)]);
    } else if (idx < 1024 * 1024 + 262144) {
        const int t = idx - 1024 * 1024;
        g_woh[t] = __float2half_rn(Wout[t]);
    } else {
        const int t = idx - 1024 * 1024 - 262144;
        const int j = t >> 9, m = t & 511;
        g_wvt[t] = __float2half_rn(Wqkv[(1024 + m) * 512 + j]);
    }
}

// reduce gram partials -> fp32 -> hi/lo fp16 pair (mirror lower triangle)
__global__ void __launch_bounds__(256) gred()
{
    const int idx = blockIdx.x * 256 + threadIdx.x;
    const int b  = idx >> 18;
    const int ij = idx & 262143;
    const int i = ij >> 9, j = ij & 511;
    const int src = ((i >> 7) > (j >> 7)) ? (j * 512 + i) : ij;
    float s = 0.f;
#pragma unroll
    for (int p = 0; p < GSPL; p++)
        s += g_gramP[((size_t)b * GSPL + p) * 262144 + src];
    const __half hi = __float2half_rn(s);
    const float  lo = s - __half2float(hi);
    g_g2[((size_t)b * 512 + i) * 1024 + j]       = hi;
    g_g2[((size_t)b * 512 + i) * 1024 + 512 + j] = __float2half_rn(lo);
}

// ---------------------------------------------------------------------------
extern "C" void kernel_launch(void* const* d_in, const int* in_sizes, int n_in,
                              void* d_out, int out_size)
{
    const float* x    = (const float*)d_in[0];
    const float* Wqkv = (const float*)d_in[1];
    const float* Wout = (const float*)d_in[2];
    const float* bout = (const float*)d_in[3];
    const float* temp = (const float*)d_in[4];
    float* out = (float*)d_out;

    cudaFuncSetAttribute(k_gram, cudaFuncAttributeMaxDynamicSharedMemorySize, BIG_SMEM);
    cudaFuncSetAttribute(k_T1,   cudaFuncAttributeMaxDynamicSharedMemorySize, BIG_SMEM);
    cudaFuncSetAttribute(k_qkp,  cudaFuncAttributeMaxDynamicSharedMemorySize, BIG_SMEM);
    cudaFuncSetAttribute(k_M,    cudaFuncAttributeMaxDynamicSharedMemorySize, BIG_SMEM);
    cudaFuncSetAttribute(k_P,    cudaFuncAttributeMaxDynamicSharedMemorySize, BIG_SMEM);
    cudaFuncSetAttribute(k_out,  cudaFuncAttributeMaxDynamicSharedMemorySize, BIG_SMEM);

    // 0. conversions / layouts (x read ONCE)
    xprep<<<dim3(Nn / 32, Cn / 32, Bn), dim3(32, 8)>>>(x);
    wprep<<<6144, 256>>>(Wqkv, Wout);

    // 1. Gram partials (triangle) + reduce/mirror/split
    k_gram<<<dim3(GSPL, 10, Bn), 128, BIG_SMEM>>>();
    gred<<<(Bn * 262144) / 256, 256>>>();

    // 2. T1 = Wqk @ G (hi+lo)
    k_T1<<<dim3(4, 8, Bn), 128, BIG_SMEM>>>();

    // 3. QK logits + diagonal norms
    k_qkp<<<16, 128, BIG_SMEM>>>();
    kdiag<<<512, 256>>>();

    // 4. softmax (normalization fused)
    softmax_kernel<<<16 * 128, 128>>>(temp);

    // 5. M = Wout_h @ attn_h
    k_M<<<dim3(1, 4, 16), 128, BIG_SMEM>>>();

    // 6. P = M @ Wv
    k_P<<<dim3(4, 4, Bn), 128, BIG_SMEM>>>();

    // 7. out = x @ P^T + bias
    k_out<<<dim3(4, 64, Bn), 128, BIG_SMEM>>>(out, bout);
}

// round 14
// speedup vs baseline: 1.5218x; 1.0627x over previous
#include <cuda_runtime.h>
#include <cuda_fp16.h>
#include <cstddef>
#include <cstdint>

#define Bn   4
#define Nn   8192
#define Cn   512
#define DHn  128
#define GSPL 8                      // gram split-K chunks (1024 tokens each)

// ---------------- scratch (device globals) ---------------------------------
__device__ __align__(128) __half g_xh  [(size_t)Bn * Nn * Cn];   // x token-major
__device__ __align__(128) __half g_xt  [(size_t)Bn * Cn * Nn];   // x channel-major
__device__ __align__(128) __half g_wqk2[1024 * 1024];            // [Wqk | Wqk] dup cols
__device__ __align__(128) __half g_woh [512 * 512];
__device__ __align__(128) __half g_wvt [512 * 512];              // Wv^T
__device__ __align__(128) float  g_gramP[(size_t)Bn * GSPL * 512 * 512];
__device__ __align__(128) __half g_g2  [Bn * 512 * 1024];        // [G_hi | G_lo] rows
__device__ __align__(128) __half g_T1  [Bn * 1024 * 512];        // Wqk @ G
__device__ __align__(128) float  g_diag[Bn * 1024];              // qq (0-511), kk (512-1023)
__device__ __align__(128) __half g_attnT[16 * DHn * DHn];        // [bh][d][c]
__device__ __align__(128) __half g_M   [Bn * Cn * Cn];           // Wout_h @ attn_h
__device__ __align__(128) __half g_P   [Bn * Cn * Cn];           // M @ Wv

// upper-triangle tile map (4x4 -> 10 tiles)
__device__ const int c_ti[10] = {0,0,0,0,1,1,1,2,2,3};
__device__ const int c_tj[10] = {0,1,2,3,1,2,3,2,3,3};

// ---------------- PTX helpers ----------------------------------------------
__device__ __forceinline__ uint32_t sptr(const void* p) {
    return (uint32_t)__cvta_generic_to_shared(p);
}
#define CPA(dst, src) asm volatile("cp.async.cg.shared.global [%0],[%1],16;\n" \
                                   :: "r"(dst), "l"(src))
#define CPC() asm volatile("cp.async.commit_group;\n")
#define CPW0() asm volatile("cp.async.wait_group 0;\n")
#define CPW1() asm volatile("cp.async.wait_group 1;\n")

__device__ __forceinline__ void ldmx4(uint32_t* r, uint32_t a) {
    asm volatile("ldmatrix.sync.aligned.m8n8.x4.shared.b16 {%0,%1,%2,%3},[%4];"
                 : "=r"(r[0]), "=r"(r[1]), "=r"(r[2]), "=r"(r[3]) : "r"(a));
}
__device__ __forceinline__ void mma16816(float* c, const uint32_t* a, const uint32_t* b) {
    asm volatile(
        "mma.sync.aligned.m16n8k16.row.col.f32.f16.f16.f32 "
        "{%0,%1,%2,%3},{%4,%5,%6,%7},{%8,%9},{%0,%1,%2,%3};"
        : "+f"(c[0]), "+f"(c[1]), "+f"(c[2]), "+f"(c[3])
        : "r"(a[0]), "r"(a[1]), "r"(a[2]), "r"(a[3]), "r"(b[0]), "r"(b[1]));
}

// ---------------------------------------------------------------------------
// Pipelined 128x128 GEMM mainloop: BK=64, 2-stage ring, one barrier per iter,
// 128 threads = 4 warps of 64x64. 2 CTAs/SM.
// ---------------------------------------------------------------------------
#define STAGE_BYTES 36864
#define BIG_SMEM    (2 * STAGE_BYTES)   // 73728

#define GEMM_MAINLOOP(A, B, K, lda, ldb, m0, n0)                               \
    const uint32_t s0 = sptr(dsm);                                             \
    const int tid  = threadIdx.x;                                              \
    const int lane = tid & 31;                                                 \
    const int wid  = tid >> 5;                                                 \
    const int wm   = (wid & 1) * 64;                                           \
    const int wn   = (wid >> 1) * 64;                                          \
    float acc[4][8][4];                                                        \
    _Pragma("unroll") for (int i = 0; i < 4; i++)                              \
    _Pragma("unroll") for (int j = 0; j < 8; j++)                              \
    _Pragma("unroll") for (int t = 0; t < 4; t++) acc[i][j][t] = 0.f;          \
    const int lrow = tid >> 3;           /* 0..15 */                           \
    const int lc16 = tid & 7;                                                  \
    const __half* Ag = (A) + (size_t)((m0) + lrow) * (lda) + lc16 * 8;         \
    const __half* Bg = (B) + (size_t)((n0) + lrow) * (ldb) + lc16 * 8;         \
    auto load_stage = [&](int stg, int k0) {                                   \
        const uint32_t ad = s0 + stg * STAGE_BYTES + lrow * 144 + lc16 * 16;   \
        const uint32_t bd = ad + 18432;                                        \
        _Pragma("unroll") for (int u = 0; u < 8; u++) {                        \
            CPA(ad + u * (16 * 144), Ag + (size_t)(u * 16) * (lda) + k0);      \
            CPA(bd + u * (16 * 144), Bg + (size_t)(u * 16) * (ldb) + k0);      \
        }                                                                      \
        CPC();                                                                 \
    };                                                                         \
    const uint32_t a_fb = (wm + (lane & 15)) * 144 + (lane >> 4) * 16;         \
    const uint32_t b_fb = 18432 +                                              \
        (wn + (lane & 7) + ((lane >> 4) * 8)) * 144 + ((lane >> 3) & 1) * 16;  \
    uint32_t af[2][4][4], bf[2][4][4];                                         \
    auto ldfrags = [&](int slot, int stg, int ks) {                            \
        const uint32_t ab = s0 + stg * STAGE_BYTES + a_fb + ks * 32;           \
        const uint32_t bb = s0 + stg * STAGE_BYTES + b_fb + ks * 32;           \
        _Pragma("unroll") for (int mi = 0; mi < 4; mi++)                       \
            ldmx4(af[slot][mi], ab + mi * (16 * 144));                         \
        _Pragma("unroll") for (int nj = 0; nj < 4; nj++)                       \
            ldmx4(bf[slot][nj], bb + nj * (16 * 144));                         \
    };                                                                         \
    auto mma_all = [&](int slot) {                                             \
        _Pragma("unroll") for (int mi = 0; mi < 4; mi++)                       \
        _Pragma("unroll") for (int nj = 0; nj < 8; nj++)                       \
            mma16816(acc[mi][nj], af[slot][mi], &bf[slot][nj >> 1][(nj & 1) * 2]); \
    };                                                                         \
    const int niter = (K) / 64;                                                \
    load_stage(0, 0);                                                          \
    load_stage(1, 64);                                                         \
    CPW1();                                                                    \
    __syncthreads();                                                           \
    ldfrags(0, 0, 0);                                                          \
    int st = 0;                                                                \
    for (int it = 0; it < niter; ++it) {                                       \
        ldfrags(1, st, 1); mma_all(0);                                         \
        ldfrags(0, st, 2); mma_all(1);                                         \
        ldfrags(1, st, 3); mma_all(0);                                         \
        if (it + 1 < niter) {                                                  \
            CPW0();                                                            \
            __syncthreads();                                                   \
            if (it + 2 < niter) load_stage(st, (it + 2) * 64);                 \
            ldfrags(0, st ^ 1, 0);                                             \
            st ^= 1;                                                           \
        }                                                                      \
        mma_all(1);                                                            \
    }

template<bool HALF_OUT, bool BIAS>
__device__ __forceinline__ void gemm_big(
    const __half* __restrict__ A, const __half* __restrict__ B,
    void* __restrict__ Cp, const float* __restrict__ bias,
    int K, int lda, int ldb, int ldc, int m0, int n0)
{
    extern __shared__ char dsm[];
    GEMM_MAINLOOP(A, B, K, lda, ldb, m0, n0)

    const int g  = lane >> 2;
    const int tg = lane & 3;
#pragma unroll
    for (int mi = 0; mi < 4; mi++) {
#pragma unroll
        for (int nj = 0; nj < 8; nj++) {
            const int r0 = m0 + wm + mi * 16 + g;
            const int cc = n0 + wn + nj * 8 + 2 * tg;
            float* a4 = acc[mi][nj];
            if (HALF_OUT) {
                __half* C = (__half*)Cp;
                *(__half2*)&C[(size_t)r0 * ldc + cc]       = __floats2half2_rn(a4[0], a4[1]);
                *(__half2*)&C[(size_t)(r0 + 8) * ldc + cc] = __floats2half2_rn(a4[2], a4[3]);
            } else {
                float* C = (float*)Cp;
                float b0 = 0.f, b1 = 0.f;
                if (BIAS) { float2 bb = *(const float2*)&bias[cc]; b0 = bb.x; b1 = bb.y; }
                *(float2*)&C[(size_t)r0 * ldc + cc]       = make_float2(a4[0] + b0, a4[1] + b1);
                *(float2*)&C[(size_t)(r0 + 8) * ldc + cc] = make_float2(a4[2] + b0, a4[3] + b1);
            }
        }
    }
}

// ---------------- GEMM kernel wrappers --------------------------------------
// 1. Gram partials (upper-triangle tiles only): grid (GSPL, 10, 4)
__global__ void __launch_bounds__(128, 2) k_gram()
{
    const int b = blockIdx.z;
    const int m0 = c_ti[blockIdx.y] * 128;
    const int n0 = c_tj[blockIdx.y] * 128;
    const __half* X = g_xt + (size_t)b * Cn * Nn + (size_t)blockIdx.x * (Nn / GSPL);
    float* C = g_gramP + ((size_t)b * GSPL + blockIdx.x) * (512 * 512);
    gemm_big<false, false>(X, X, C, nullptr, Nn / GSPL, Nn, Nn, 512, m0, n0);
}

// 2. T1 = Wqk @ G  (hi+lo via duplicated-K operands), half out
__global__ void __launch_bounds__(128, 2) k_T1()
{
    const int b = blockIdx.z;
    const __half* Bg = g_g2 + (size_t)b * 512 * 1024;
    __half* C = g_T1 + (size_t)b * 1024 * 512;
    gemm_big<true, false>(g_wqk2, Bg, C, nullptr, 1024, 1024, 1024, 512,
                          blockIdx.y * 128, blockIdx.x * 128);
}

// 3b. diag dots: g_diag[b*1024+r] = dot(T1[b] row r, Wqk row r)  (warp per row)
__global__ void __launch_bounds__(256) kdiag()
{
    const int gw = blockIdx.x * 8 + (threadIdx.x >> 5);   // 0..4095
    const int b = gw >> 10, r = gw & 1023;
    const int lane = threadIdx.x & 31;
    const __half2* t1 = (const __half2*)(g_T1 + ((size_t)b * 1024 + r) * 512);
    const __half2* wr = (const __half2*)(g_wqk2 + (size_t)r * 1024);
    float s = 0.f;
#pragma unroll
    for (int k = lane; k < 256; k += 32) {
        float2 a = __half22float2(t1[k]);
        float2 w = __half22float2(wr[k]);
        s = fmaf(a.x, w.x, fmaf(a.y, w.y, s));
    }
#pragma unroll
    for (int off = 16; off; off >>= 1)
        s += __shfl_xor_sync(0xffffffffu, s, off);
    if (lane == 0) g_diag[gw] = s;
}

// 3. QK logits per bh WITH FUSED softmax epilogue; writes attnT[bh][d][c].
//    grid 16, 128 threads, 2 CTAs/SM.
__global__ void __launch_bounds__(128, 2) k_qkp(const float* __restrict__ temp)
{
    extern __shared__ char dsm[];
    const int bh = blockIdx.x;
    const int b = bh >> 2, h = bh & 3;
    const __half* A  = g_T1 + (size_t)b * 1024 * 512 + (size_t)(h * DHn) * 512;
    const __half* Bp = g_wqk2 + (size_t)(512 + h * DHn) * 1024;

    GEMM_MAINLOOP(A, Bp, 512, 512, 1024, 0, 0)

    // ---- fused softmax over d ----
    float* buf = (float*)dsm;                 // [128][129] raw logits
    float* sqv = (float*)(dsm + 128 * 129 * 4);   // qinv[128]
    float* skv = sqv + 128;                        // kinv[128]
    const int g  = lane >> 2;
    const int tg = lane & 3;
    __syncthreads();                          // stage smem dead
#pragma unroll
    for (int mi = 0; mi < 4; mi++) {
#pragma unroll
        for (int nj = 0; nj < 8; nj++) {
            const int r0 = wm + mi * 16 + g;
            const int cc = wn + nj * 8 + 2 * tg;
            float* a4 = acc[mi][nj];
            buf[r0 * 129 + cc]           = a4[0];
            buf[r0 * 129 + cc + 1]       = a4[1];
            buf[(r0 + 8) * 129 + cc]     = a4[2];
            buf[(r0 + 8) * 129 + cc + 1] = a4[3];
        }
    }
    {
        const float qq = g_diag[b * 1024 + h * DHn + tid];
        const float kk = g_diag[b * 1024 + 512 + h * DHn + tid];
        sqv[tid] = 1.f / fmaxf(sqrtf(fmaxf(qq, 0.f)), 1e-12f);
        skv[tid] = 1.f / fmaxf(sqrtf(fmaxf(kk, 0.f)), 1e-12f);
    }
    __syncthreads();

    const int c = tid;
    const float qs = sqv[c] * temp[h];
    float mx = -1e30f;
#pragma unroll 8
    for (int d = 0; d < 128; d++)
        mx = fmaxf(mx, buf[c * 129 + d] * skv[d]);
    float sum = 0.f;
#pragma unroll 8
    for (int d = 0; d < 128; d++) {
        const float e = expf(qs * (buf[c * 129 + d] * skv[d] - mx));
        buf[c * 129 + d] = e;
        sum += e;
    }
    const float inv = 1.f / sum;
    __half* dst = g_attnT + (size_t)bh * (DHn * DHn) + c;
#pragma unroll 8
    for (int d = 0; d < 128; d++)
        dst[d * DHn] = __float2half_rn(buf[c * 129 + d] * inv);
}

// 5. M_b[j][h*128+d] = Wout_h @ attn_bh   grid (1, 4, 16)
__global__ void __launch_bounds__(128, 2) k_M()
{
    const int bh = blockIdx.z;
    const int b = bh >> 2, h = bh & 3;
    const __half* A  = g_woh + h * DHn;
    const __half* Bt = g_attnT + (size_t)bh * DHn * DHn;
    __half* C = g_M + (size_t)b * Cn * Cn + h * DHn;
    gemm_big<true, false>(A, Bt, C, nullptr, DHn, 512, DHn, Cn,
                          blockIdx.y * 128, 0);
}

// 6. P_b = M_b @ Wv, half out. grid (4, 4, 4)
__global__ void __launch_bounds__(128, 2) k_P()
{
    const int b = blockIdx.z;
    const __half* A = g_M + (size_t)b * Cn * Cn;
    __half* C = g_P + (size_t)b * Cn * Cn;
    gemm_big<true, false>(A, g_wvt, C, nullptr, 512, 512, 512, 512,
                          blockIdx.y * 128, blockIdx.x * 128);
}

// 7. out = x @ P^T + bias   grid (4 j-tiles, 64 n-tiles, 4 batches)
__global__ void __launch_bounds__(128, 2) k_out(float* __restrict__ out,
                                                const float* __restrict__ bias)
{
    const int b = blockIdx.z;
    const __half* A = g_xh + (size_t)b * Nn * Cn;
    const __half* Bp = g_P + (size_t)b * Cn * Cn;
    float* C = out + (size_t)b * Nn * Cn;
    gemm_big<false, true>(A, Bp, C, bias, 512, 512, 512, 512,
                          blockIdx.y * 128, blockIdx.x * 128);
}

// ---------------- small kernels ---------------------------------------------
// x [b][n][c] fp32 -> g_xh [b][n][c] fp16 AND g_xt [b][c][n] fp16 (read once)
__global__ void __launch_bounds__(256) xprep(const float* __restrict__ x)
{
    __shared__ __half ts[32][33];
    const int n0 = blockIdx.x * 32, c0 = blockIdx.y * 32, b = blockIdx.z;
    const int tx = threadIdx.x, ty = threadIdx.y;
#pragma unroll
    for (int r = 0; r < 4; r++) {
        const size_t idx = ((size_t)b * Nn + n0 + ty + r * 8) * Cn + c0 + tx;
        const __half hv = __float2half_rn(x[idx]);
        g_xh[idx] = hv;
        ts[ty + r * 8][tx] = hv;
    }
    __syncthreads();
#pragma unroll
    for (int r = 0; r < 4; r++)
        g_xt[((size_t)b * Cn + c0 + ty + r * 8) * Nn + n0 + tx] = ts[tx][ty + r * 8];
}

// weights prep: wqk2 (dup cols), woh, wvt (= Wv^T)
__global__ void __launch_bounds__(256) wprep(const float* __restrict__ Wqkv,
                                             const float* __restrict__ Wout)
{
    const int idx = blockIdx.x * 256 + threadIdx.x;
    if (idx < 1024 * 1024) {
        const int m = idx >> 10, k = idx & 1023;
        g_wqk2[idx] = __float2half_rn(Wqkv[m * 512 + (k & 511)]);
    } else if (idx < 1024 * 1024 + 262144) {
        const int t = idx - 1024 * 1024;
        g_woh[t] = __float2half_rn(Wout[t]);
    } else {
        const int t = idx - 1024 * 1024 - 262144;
        const int j = t >> 9, m = t & 511;
        g_wvt[t] = __float2half_rn(Wqkv[(1024 + m) * 512 + j]);
    }
}

// reduce gram partials -> hi/lo fp16 pair, tiled + coalesced mirror.
// grid (16 subtiles, 10 tiles, 4 b), block (32, 8).
__global__ void __launch_bounds__(256) gred_t()
{
    __shared__ float sh[32][33];
    const int b  = blockIdx.z;
    const int ti = c_ti[blockIdx.y], tj = c_tj[blockIdx.y];
    const int si = (blockIdx.x >> 2) * 32, sj = (blockIdx.x & 3) * 32;
    const int i0 = ti * 128 + si, j0 = tj * 128 + sj;
    const int tx = threadIdx.x, ty = threadIdx.y;
    const float* gp = g_gramP + (size_t)b * GSPL * 262144;

#pragma unroll
    for (int r = 0; r < 4; r++) {
        const int i = i0 + ty + r * 8;
        const int j = j0 + tx;
        float s = 0.f;
#pragma unroll
        for (int p = 0; p < GSPL; p++)
            s += gp[(size_t)p * 262144 + i * 512 + j];
        const __half hi = __float2half_rn(s);
        g_g2[((size_t)b * 512 + i) * 1024 + j]       = hi;
        g_g2[((size_t)b * 512 + i) * 1024 + 512 + j] =
            __float2half_rn(s - __half2float(hi));
        sh[ty + r * 8][tx] = s;
    }
    if (ti == tj) return;        // diagonal tile covers both halves already
    __syncthreads();
#pragma unroll
    for (int r = 0; r < 4; r++) {
        const int jj = j0 + ty + r * 8;    // row in mirrored output
        const int ii = i0 + tx;
        const float s = sh[tx][ty + r * 8];
        const __half hi = __float2half_rn(s);
        g_g2[((size_t)b * 512 + jj) * 1024 + ii]       = hi;
        g_g2[((size_t)b * 512 + jj) * 1024 + 512 + ii] =
            __float2half_rn(s - __half2float(hi));
    }
}

// ---------------------------------------------------------------------------
extern "C" void kernel_launch(void* const* d_in, const int* in_sizes, int n_in,
                              void* d_out, int out_size)
{
    const float* x    = (const float*)d_in[0];
    const float* Wqkv = (const float*)d_in[1];
    const float* Wout = (const float*)d_in[2];
    const float* bout = (const float*)d_in[3];
    const float* temp = (const float*)d_in[4];
    float* out = (float*)d_out;

    cudaFuncSetAttribute(k_gram, cudaFuncAttributeMaxDynamicSharedMemorySize, BIG_SMEM);
    cudaFuncSetAttribute(k_T1,   cudaFuncAttributeMaxDynamicSharedMemorySize, BIG_SMEM);
    cudaFuncSetAttribute(k_qkp,  cudaFuncAttributeMaxDynamicSharedMemorySize, BIG_SMEM);
    cudaFuncSetAttribute(k_M,    cudaFuncAttributeMaxDynamicSharedMemorySize, BIG_SMEM);
    cudaFuncSetAttribute(k_P,    cudaFuncAttributeMaxDynamicSharedMemorySize, BIG_SMEM);
    cudaFuncSetAttribute(k_out,  cudaFuncAttributeMaxDynamicSharedMemorySize, BIG_SMEM);

    // 0. conversions / layouts (x read ONCE)
    xprep<<<dim3(Nn / 32, Cn / 32, Bn), dim3(32, 8)>>>(x);
    wprep<<<6144, 256>>>(Wqkv, Wout);

    // 1. Gram partials (triangle) + coalesced reduce/mirror/split
    k_gram<<<dim3(GSPL, 10, Bn), 128, BIG_SMEM>>>();
    gred_t<<<dim3(16, 10, Bn), dim3(32, 8)>>>();

    // 2. T1 = Wqk @ G (hi+lo)
    k_T1<<<dim3(4, 8, Bn), 128, BIG_SMEM>>>();

    // 3. diagonal norms, then logits GEMM with fused softmax
    kdiag<<<512, 256>>>();
    k_qkp<<<16, 128, BIG_SMEM>>>(temp);

    // 5. M = Wout_h @ attn_h
    k_M<<<dim3(1, 4, 16), 128, BIG_SMEM>>>();

    // 6. P = M @ Wv
    k_P<<<dim3(4, 4, Bn), 128, BIG_SMEM>>>();

    // 7. out = x @ P^T + bias
    k_out<<<dim3(4, 64, Bn), 128, BIG_SMEM>>>(out, bout);
}

// round 15
// speedup vs baseline: 1.6067x; 1.0558x over previous
#include <cuda_runtime.h>
#include <cuda_fp16.h>
#include <cstddef>
#include <cstdint>

#define Bn   4
#define Nn   8192
#define Cn   512
#define DHn  128
#define GSPL 8

// ---------------- scratch (device globals) ---------------------------------
__device__ __align__(128) __half g_xh  [(size_t)Bn * Nn * Cn];
__device__ __align__(128) __half g_xt  [(size_t)Bn * Cn * Nn];
__device__ __align__(128) __half g_wqk2[1024 * 1024];
__device__ __align__(128) __half g_woh [512 * 512];
__device__ __align__(128) __half g_wvt [512 * 512];
__device__ __align__(128) float  g_gramP[(size_t)Bn * GSPL * 512 * 512];
__device__ __align__(128) __half g_g2  [Bn * 512 * 1024];
__device__ __align__(128) __half g_T1  [Bn * 1024 * 512];
__device__ __align__(128) float  g_diag[Bn * 1024];
__device__ __align__(128) float  g_qkP [4 * 16 * DHn * DHn];     // split-K partials
__device__ __align__(128) __half g_attnT[16 * DHn * DHn];
__device__ __align__(128) __half g_M   [Bn * Cn * Cn];
__device__ __align__(128) __half g_P   [Bn * Cn * Cn];

__device__ const int c_ti[10] = {0,0,0,0,1,1,1,2,2,3};
__device__ const int c_tj[10] = {0,1,2,3,1,2,3,2,3,3};

// ---------------- PTX helpers ----------------------------------------------
__device__ __forceinline__ uint32_t sptr(const void* p) {
    return (uint32_t)__cvta_generic_to_shared(p);
}
#define CPA(dst, src) asm volatile("cp.async.cg.shared.global [%0],[%1],16;\n" \
                                   :: "r"(dst), "l"(src))
#define CPC() asm volatile("cp.async.commit_group;\n")
#define CPW0() asm volatile("cp.async.wait_group 0;\n")
#define CPW1() asm volatile("cp.async.wait_group 1;\n")

__device__ __forceinline__ void ldmx4(uint32_t* r, uint32_t a) {
    asm volatile("ldmatrix.sync.aligned.m8n8.x4.shared.b16 {%0,%1,%2,%3},[%4];"
                 : "=r"(r[0]), "=r"(r[1]), "=r"(r[2]), "=r"(r[3]) : "r"(a));
}
__device__ __forceinline__ void mma16816(float* c, const uint32_t* a, const uint32_t* b) {
    asm volatile(
        "mma.sync.aligned.m16n8k16.row.col.f32.f16.f16.f32 "
        "{%0,%1,%2,%3},{%4,%5,%6,%7},{%8,%9},{%0,%1,%2,%3};"
        : "+f"(c[0]), "+f"(c[1]), "+f"(c[2]), "+f"(c[3])
        : "r"(a[0]), "r"(a[1]), "r"(a[2]), "r"(a[3]), "r"(b[0]), "r"(b[1]));
}

// ---------------------------------------------------------------------------
// Variant L: 128x128 CTA tile (throughput kernels: k_gram, k_out)
// ---------------------------------------------------------------------------
#define STAGE_BYTES 36864
#define BIG_SMEM    (2 * STAGE_BYTES)   // 73728

#define GEMM_MAINLOOP(A, B, K, lda, ldb, m0, n0)                               \
    const uint32_t s0 = sptr(dsm);                                             \
    const int tid  = threadIdx.x;                                              \
    const int lane = tid & 31;                                                 \
    const int wid  = tid >> 5;                                                 \
    const int wm   = (wid & 1) * 64;                                           \
    const int wn   = (wid >> 1) * 64;                                          \
    float acc[4][8][4];                                                        \
    _Pragma("unroll") for (int i = 0; i < 4; i++)                              \
    _Pragma("unroll") for (int j = 0; j < 8; j++)                              \
    _Pragma("unroll") for (int t = 0; t < 4; t++) acc[i][j][t] = 0.f;          \
    const int lrow = tid >> 3;                                                 \
    const int lc16 = tid & 7;                                                  \
    const __half* Ag = (A) + (size_t)((m0) + lrow) * (lda) + lc16 * 8;         \
    const __half* Bg = (B) + (size_t)((n0) + lrow) * (ldb) + lc16 * 8;         \
    auto load_stage = [&](int stg, int k0) {                                   \
        const uint32_t ad = s0 + stg * STAGE_BYTES + lrow * 144 + lc16 * 16;   \
        const uint32_t bd = ad + 18432;                                        \
        _Pragma("unroll") for (int u = 0; u < 8; u++) {                        \
            CPA(ad + u * (16 * 144), Ag + (size_t)(u * 16) * (lda) + k0);      \
            CPA(bd + u * (16 * 144), Bg + (size_t)(u * 16) * (ldb) + k0);      \
        }                                                                      \
        CPC();                                                                 \
    };                                                                         \
    const uint32_t a_fb = (wm + (lane & 15)) * 144 + (lane >> 4) * 16;         \
    const uint32_t b_fb = 18432 +                                              \
        (wn + (lane & 7) + ((lane >> 4) * 8)) * 144 + ((lane >> 3) & 1) * 16;  \
    uint32_t af[2][4][4], bf[2][4][4];                                         \
    auto ldfrags = [&](int slot, int stg, int ks) {                            \
        const uint32_t ab = s0 + stg * STAGE_BYTES + a_fb + ks * 32;           \
        const uint32_t bb = s0 + stg * STAGE_BYTES + b_fb + ks * 32;           \
        _Pragma("unroll") for (int mi = 0; mi < 4; mi++)                       \
            ldmx4(af[slot][mi], ab + mi * (16 * 144));                         \
        _Pragma("unroll") for (int nj = 0; nj < 4; nj++)                       \
            ldmx4(bf[slot][nj], bb + nj * (16 * 144));                         \
    };                                                                         \
    auto mma_all = [&](int slot) {                                             \
        _Pragma("unroll") for (int mi = 0; mi < 4; mi++)                       \
        _Pragma("unroll") for (int nj = 0; nj < 8; nj++)                       \
            mma16816(acc[mi][nj], af[slot][mi], &bf[slot][nj >> 1][(nj & 1) * 2]); \
    };                                                                         \
    const int niter = (K) / 64;                                                \
    load_stage(0, 0);                                                          \
    load_stage(1, 64);                                                         \
    CPW1();                                                                    \
    __syncthreads();                                                           \
    ldfrags(0, 0, 0);                                                          \
    int st = 0;                                                                \
    for (int it = 0; it < niter; ++it) {                                       \
        ldfrags(1, st, 1); mma_all(0);                                         \
        ldfrags(0, st, 2); mma_all(1);                                         \
        ldfrags(1, st, 3); mma_all(0);                                         \
        if (it + 1 < niter) {                                                  \
            CPW0();                                                            \
            __syncthreads();                                                   \
            if (it + 2 < niter) load_stage(st, (it + 2) * 64);                 \
            ldfrags(0, st ^ 1, 0);                                             \
            st ^= 1;                                                           \
        }                                                                      \
        mma_all(1);                                                            \
    }

template<bool HALF_OUT, bool BIAS>
__device__ __forceinline__ void gemm_big(
    const __half* __restrict__ A, const __half* __restrict__ B,
    void* __restrict__ Cp, const float* __restrict__ bias,
    int K, int lda, int ldb, int ldc, int m0, int n0)
{
    extern __shared__ char dsm[];
    GEMM_MAINLOOP(A, B, K, lda, ldb, m0, n0)

    const int g  = lane >> 2;
    const int tg = lane & 3;
#pragma unroll
    for (int mi = 0; mi < 4; mi++) {
#pragma unroll
        for (int nj = 0; nj < 8; nj++) {
            const int r0 = m0 + wm + mi * 16 + g;
            const int cc = n0 + wn + nj * 8 + 2 * tg;
            float* a4 = acc[mi][nj];
            if (HALF_OUT) {
                __half* C = (__half*)Cp;
                *(__half2*)&C[(size_t)r0 * ldc + cc]       = __floats2half2_rn(a4[0], a4[1]);
                *(__half2*)&C[(size_t)(r0 + 8) * ldc + cc] = __floats2half2_rn(a4[2], a4[3]);
            } else {
                float* C = (float*)Cp;
                float b0 = 0.f, b1 = 0.f;
                if (BIAS) { float2 bb = *(const float2*)&bias[cc]; b0 = bb.x; b1 = bb.y; }
                *(float2*)&C[(size_t)r0 * ldc + cc]       = make_float2(a4[0] + b0, a4[1] + b1);
                *(float2*)&C[(size_t)(r0 + 8) * ldc + cc] = make_float2(a4[2] + b0, a4[3] + b1);
            }
        }
    }
}

// ---------------------------------------------------------------------------
// Variant S: 64x128 CTA tile (latency kernels: k_T1, k_qkp, k_M, k_P)
// Stage: A 64x144B (+0), B 128x144B (+9216). 128 threads, 4 warps of 64x32.
// ---------------------------------------------------------------------------
#define STAGE_S  27648
#define SMEM_S   (2 * STAGE_S)   // 55296

#define GEMM_MAINLOOP_S(A, B, K, lda, ldb, m0, n0)                             \
    const uint32_t s0 = sptr(dsm);                                             \
    const int tid  = threadIdx.x;                                              \
    const int lane = tid & 31;                                                 \
    const int wid  = tid >> 5;                                                 \
    const int wn   = wid * 32;                                                 \
    float acc[4][4][4];                                                        \
    _Pragma("unroll") for (int i = 0; i < 4; i++)                              \
    _Pragma("unroll") for (int j = 0; j < 4; j++)                              \
    _Pragma("unroll") for (int t = 0; t < 4; t++) acc[i][j][t] = 0.f;          \
    const int lrow = tid >> 3;                                                 \
    const int lc16 = tid & 7;                                                  \
    const __half* Ag = (A) + (size_t)((m0) + lrow) * (lda) + lc16 * 8;         \
    const __half* Bg = (B) + (size_t)((n0) + lrow) * (ldb) + lc16 * 8;         \
    auto load_stage = [&](int stg, int k0) {                                   \
        const uint32_t ad = s0 + stg * STAGE_S + lrow * 144 + lc16 * 16;       \
        const uint32_t bd = ad + 9216;                                         \
        _Pragma("unroll") for (int u = 0; u < 4; u++)                          \
            CPA(ad + u * (16 * 144), Ag + (size_t)(u * 16) * (lda) + k0);      \
        _Pragma("unroll") for (int u = 0; u < 8; u++)                          \
            CPA(bd + u * (16 * 144), Bg + (size_t)(u * 16) * (ldb) + k0);      \
        CPC();                                                                 \
    };                                                                         \
    const uint32_t a_fb = (lane & 15) * 144 + (lane >> 4) * 16;                \
    const uint32_t b_fb = 9216 +                                               \
        (wn + (lane & 7) + ((lane >> 4) * 8)) * 144 + ((lane >> 3) & 1) * 16;  \
    uint32_t af[2][4][4], bf[2][2][4];                                         \
    auto ldfrags = [&](int slot, int stg, int ks) {                            \
        const uint32_t ab = s0 + stg * STAGE_S + a_fb + ks * 32;               \
        const uint32_t bb = s0 + stg * STAGE_S + b_fb + ks * 32;               \
        _Pragma("unroll") for (int mi = 0; mi < 4; mi++)                       \
            ldmx4(af[slot][mi], ab + mi * (16 * 144));                         \
        _Pragma("unroll") for (int nj = 0; nj < 2; nj++)                       \
            ldmx4(bf[slot][nj], bb + nj * (16 * 144));                         \
    };                                                                         \
    auto mma_all = [&](int slot) {                                             \
        _Pragma("unroll") for (int mi = 0; mi < 4; mi++)                       \
        _Pragma("unroll") for (int nj = 0; nj < 4; nj++)                       \
            mma16816(acc[mi][nj], af[slot][mi], &bf[slot][nj >> 1][(nj & 1) * 2]); \
    };                                                                         \
    const int niter = (K) / 64;                                                \
    load_stage(0, 0);                                                          \
    load_stage(1, 64);                                                         \
    CPW1();                                                                    \
    __syncthreads();                                                           \
    ldfrags(0, 0, 0);                                                          \
    int st = 0;                                                                \
    for (int it = 0; it < niter; ++it) {                                       \
        ldfrags(1, st, 1); mma_all(0);                                         \
        ldfrags(0, st, 2); mma_all(1);                                         \
        ldfrags(1, st, 3); mma_all(0);                                         \
        if (it + 1 < niter) {                                                  \
            CPW0();                                                            \
            __syncthreads();                                                   \
            if (it + 2 < niter) load_stage(st, (it + 2) * 64);                 \
            ldfrags(0, st ^ 1, 0);                                             \
            st ^= 1;                                                           \
        }                                                                      \
        mma_all(1);                                                            \
    }

template<bool HALF_OUT>
__device__ __forceinline__ void gemm_small(
    const __half* __restrict__ A, const __half* __restrict__ B,
    void* __restrict__ Cp,
    int K, int lda, int ldb, int ldc, int m0, int n0)
{
    extern __shared__ char dsm[];
    GEMM_MAINLOOP_S(A, B, K, lda, ldb, m0, n0)

    const int g  = lane >> 2;
    const int tg = lane & 3;
#pragma unroll
    for (int mi = 0; mi < 4; mi++) {
#pragma unroll
        for (int nj = 0; nj < 4; nj++) {
            const int r0 = m0 + mi * 16 + g;
            const int cc = n0 + wn + nj * 8 + 2 * tg;
            float* a4 = acc[mi][nj];
            if (HALF_OUT) {
                __half* C = (__half*)Cp;
                *(__half2*)&C[(size_t)r0 * ldc + cc]       = __floats2half2_rn(a4[0], a4[1]);
                *(__half2*)&C[(size_t)(r0 + 8) * ldc + cc] = __floats2half2_rn(a4[2], a4[3]);
            } else {
                float* C = (float*)Cp;
                *(float2*)&C[(size_t)r0 * ldc + cc]       = make_float2(a4[0], a4[1]);
                *(float2*)&C[(size_t)(r0 + 8) * ldc + cc] = make_float2(a4[2], a4[3]);
            }
        }
    }
}

// ---------------- GEMM kernels -----------------------------------------------
// 1. Gram partials (upper-triangle tiles): grid (GSPL, 10, 4)
__global__ void __launch_bounds__(128, 2) k_gram()
{
    const int b = blockIdx.z;
    const int m0 = c_ti[blockIdx.y] * 128;
    const int n0 = c_tj[blockIdx.y] * 128;
    const __half* X = g_xt + (size_t)b * Cn * Nn + (size_t)blockIdx.x * (Nn / GSPL);
    float* C = g_gramP + ((size_t)b * GSPL + blockIdx.x) * (512 * 512);
    gemm_big<false, false>(X, X, C, nullptr, Nn / GSPL, Nn, Nn, 512, m0, n0);
}

// 2. T1 = Wqk @ G (hi+lo), half out.  grid (4 nt, 16 mt, 4 b), S-variant.
__global__ void __launch_bounds__(128, 3) k_T1()
{
    const int b = blockIdx.z;
    const __half* Bg = g_g2 + (size_t)b * 512 * 1024;
    __half* C = g_T1 + (size_t)b * 1024 * 512;
    gemm_small<true>(g_wqk2, Bg, C, 1024, 1024, 1024, 512,
                     blockIdx.y * 64, blockIdx.x * 128);
}

// 3a. diag dots (warp per row)
__global__ void __launch_bounds__(256) kdiag()
{
    const int gw = blockIdx.x * 8 + (threadIdx.x >> 5);
    const int b = gw >> 10, r = gw & 1023;
    const int lane = threadIdx.x & 31;
    const __half2* t1 = (const __half2*)(g_T1 + ((size_t)b * 1024 + r) * 512);
    const __half2* wr = (const __half2*)(g_wqk2 + (size_t)r * 1024);
    float s = 0.f;
#pragma unroll
    for (int k = lane; k < 256; k += 32) {
        float2 a = __half22float2(t1[k]);
        float2 w = __half22float2(wr[k]);
        s = fmaf(a.x, w.x, fmaf(a.y, w.y, s));
    }
#pragma unroll
    for (int off = 16; off; off >>= 1)
        s += __shfl_xor_sync(0xffffffffu, s, off);
    if (lane == 0) g_diag[gw] = s;
}

// 3b. QK logits split-K partials: grid (4 splits, 2 mt, 16 bh), S-variant, K=128
__global__ void __launch_bounds__(128, 3) k_qkp()
{
    const int s4 = blockIdx.x;
    const int mt = blockIdx.y;
    const int bh = blockIdx.z;
    const int b = bh >> 2, h = bh & 3;
    const __half* A = g_T1 + (size_t)b * 1024 * 512
                    + (size_t)(h * DHn + mt * 64) * 512 + s4 * 128;
    const __half* Bp = g_wqk2 + (size_t)(512 + h * DHn) * 1024 + s4 * 128;
    float* C = g_qkP + ((size_t)s4 * 16 + bh) * (DHn * DHn) + mt * 64 * DHn;
    gemm_small<false>(A, Bp, C, 128, 512, 1024, DHn, 0, 0);
}

// 4. softmax over d: sum partials + normalize; writes attnT[bh][d][c]
__global__ void __launch_bounds__(128) softmax_kernel(const float* __restrict__ temp)
{
    const int bh = blockIdx.x >> 7;
    const int c  = blockIdx.x & 127;
    const int b  = bh >> 2, h = bh & 3;
    const int d  = threadIdx.x;

    float s = 0.f;
#pragma unroll
    for (int p = 0; p < 4; p++)
        s += g_qkP[((size_t)p * 16 + bh) * (DHn * DHn) + c * DHn + d];

    const float qq = g_diag[b * 1024 + h * DHn + c];
    const float kk = g_diag[b * 1024 + 512 + h * DHn + d];
    const float qinv = 1.f / fmaxf(sqrtf(fmaxf(qq, 0.f)), 1e-12f);
    const float kinv = 1.f / fmaxf(sqrtf(fmaxf(kk, 0.f)), 1e-12f);
    const float val  = s * qinv * kinv * temp[h];

    __shared__ float red[128];
    red[d] = val;
    __syncthreads();
    for (int off = 64; off; off >>= 1) {
        if (d < off) red[d] = fmaxf(red[d], red[d + off]);
        __syncthreads();
    }
    const float mx = red[0];
    __syncthreads();
    const float e = expf(val - mx);
    red[d] = e;
    __syncthreads();
    for (int off = 64; off; off >>= 1) {
        if (d < off) red[d] += red[d + off];
        __syncthreads();
    }
    g_attnT[(size_t)bh * (DHn * DHn) + d * DHn + c] = __float2half_rn(e / red[0]);
}

// 5. M_b[j][h*128+d] = Wout_h @ attn_bh   grid (1, 8 mt, 16 bh), S, K=128
__global__ void __launch_bounds__(128, 3) k_M()
{
    const int bh = blockIdx.z;
    const int b = bh >> 2, h = bh & 3;
    const __half* A  = g_woh + h * DHn;
    const __half* Bt = g_attnT + (size_t)bh * DHn * DHn;
    __half* C = g_M + (size_t)b * Cn * Cn + h * DHn;
    gemm_small<true>(A, Bt, C, DHn, 512, DHn, Cn, blockIdx.y * 64, 0);
}

// 6. P_b = M_b @ Wv, half out. grid (4 nt, 8 mt, 4 b), S, K=512
__global__ void __launch_bounds__(128, 3) k_P()
{
    const int b = blockIdx.z;
    const __half* A = g_M + (size_t)b * Cn * Cn;
    __half* C = g_P + (size_t)b * Cn * Cn;
    gemm_small<true>(A, g_wvt, C, 512, 512, 512, 512,
                     blockIdx.y * 64, blockIdx.x * 128);
}

// 7. out = x @ P^T + bias   grid (4, 64, 4), L-variant
__global__ void __launch_bounds__(128, 2) k_out(float* __restrict__ out,
                                                const float* __restrict__ bias)
{
    const int b = blockIdx.z;
    const __half* A = g_xh + (size_t)b * Nn * Cn;
    const __half* Bp = g_P + (size_t)b * Cn * Cn;
    float* C = out + (size_t)b * Nn * Cn;
    gemm_big<false, true>(A, Bp, C, bias, 512, 512, 512, 512,
                          blockIdx.y * 128, blockIdx.x * 128);
}

// ---------------- small kernels ---------------------------------------------
__global__ void __launch_bounds__(256) xprep(const float* __restrict__ x)
{
    __shared__ __half ts[32][33];
    const int n0 = blockIdx.x * 32, c0 = blockIdx.y * 32, b = blockIdx.z;
    const int tx = threadIdx.x, ty = threadIdx.y;
#pragma unroll
    for (int r = 0; r < 4; r++) {
        const size_t idx = ((size_t)b * Nn + n0 + ty + r * 8) * Cn + c0 + tx;
        const __half hv = __float2half_rn(x[idx]);
        g_xh[idx] = hv;
        ts[ty + r * 8][tx] = hv;
    }
    __syncthreads();
#pragma unroll
    for (int r = 0; r < 4; r++)
        g_xt[((size_t)b * Cn + c0 + ty + r * 8) * Nn + n0 + tx] = ts[tx][ty + r * 8];
}

__global__ void __launch_bounds__(256) wprep(const float* __restrict__ Wqkv,
                                             const float* __restrict__ Wout)
{
    const int idx = blockIdx.x * 256 + threadIdx.x;
    if (idx < 1024 * 1024) {
        const int m = idx >> 10, k = idx & 1023;
        g_wqk2[idx] = __float2half_rn(Wqkv[m * 512 + (k & 511)]);
    } else if (idx < 1024 * 1024 + 262144) {
        const int t = idx - 1024 * 1024;
        g_woh[t] = __float2half_rn(Wout[t]);
    } else {
        const int t = idx - 1024 * 1024 - 262144;
        const int j = t >> 9, m = t & 511;
        g_wvt[t] = __float2half_rn(Wqkv[(1024 + m) * 512 + j]);
    }
}

// reduce gram partials -> hi/lo fp16 pair, coalesced mirror
__global__ void __launch_bounds__(256) gred_t()
{
    __shared__ float sh[32][33];
    const int b  = blockIdx.z;
    const int ti = c_ti[blockIdx.y], tj = c_tj[blockIdx.y];
    const int si = (blockIdx.x >> 2) * 32, sj = (blockIdx.x & 3) * 32;
    const int i0 = ti * 128 + si, j0 = tj * 128 + sj;
    const int tx = threadIdx.x, ty = threadIdx.y;
    const float* gp = g_gramP + (size_t)b * GSPL * 262144;

#pragma unroll
    for (int r = 0; r < 4; r++) {
        const int i = i0 + ty + r * 8;
        const int j = j0 + tx;
        float s = 0.f;
#pragma unroll
        for (int p = 0; p < GSPL; p++)
            s += gp[(size_t)p * 262144 + i * 512 + j];
        const __half hi = __float2half_rn(s);
        g_g2[((size_t)b * 512 + i) * 1024 + j]       = hi;
        g_g2[((size_t)b * 512 + i) * 1024 + 512 + j] =
            __float2half_rn(s - __half2float(hi));
        sh[ty + r * 8][tx] = s;
    }
    if (ti == tj) return;
    __syncthreads();
#pragma unroll
    for (int r = 0; r < 4; r++) {
        const int jj = j0 + ty + r * 8;
        const int ii = i0 + tx;
        const float s = sh[tx][ty + r * 8];
        const __half hi = __float2half_rn(s);
        g_g2[((size_t)b * 512 + jj) * 1024 + ii]       = hi;
        g_g2[((size_t)b * 512 + jj) * 1024 + 512 + ii] =
            __float2half_rn(s - __half2float(hi));
    }
}

// ---------------------------------------------------------------------------
extern "C" void kernel_launch(void* const* d_in, const int* in_sizes, int n_in,
                              void* d_out, int out_size)
{
    const float* x    = (const float*)d_in[0];
    const float* Wqkv = (const float*)d_in[1];
    const float* Wout = (const float*)d_in[2];
    const float* bout = (const float*)d_in[3];
    const float* temp = (const float*)d_in[4];
    float* out = (float*)d_out;

    cudaFuncSetAttribute(k_gram, cudaFuncAttributeMaxDynamicSharedMemorySize, BIG_SMEM);
    cudaFuncSetAttribute(k_out,  cudaFuncAttributeMaxDynamicSharedMemorySize, BIG_SMEM);
    cudaFuncSetAttribute(k_T1,   cudaFuncAttributeMaxDynamicSharedMemorySize, SMEM_S);
    cudaFuncSetAttribute(k_qkp,  cudaFuncAttributeMaxDynamicSharedMemorySize, SMEM_S);
    cudaFuncSetAttribute(k_M,    cudaFuncAttributeMaxDynamicSharedMemorySize, SMEM_S);
    cudaFuncSetAttribute(k_P,    cudaFuncAttributeMaxDynamicSharedMemorySize, SMEM_S);

    // 0. conversions / layouts
    xprep<<<dim3(Nn / 32, Cn / 32, Bn), dim3(32, 8)>>>(x);
    wprep<<<6144, 256>>>(Wqkv, Wout);

    // 1. Gram partials (triangle) + coalesced reduce/mirror/split
    k_gram<<<dim3(GSPL, 10, Bn), 128, BIG_SMEM>>>();
    gred_t<<<dim3(16, 10, Bn), dim3(32, 8)>>>();

    // 2. T1 = Wqk @ G (hi+lo), latency-shaped
    k_T1<<<dim3(4, 16, Bn), 128, SMEM_S>>>();

    // 3. diagonal norms + split-K logits partials
    kdiag<<<512, 256>>>();
    k_qkp<<<dim3(4, 2, 16), 128, SMEM_S>>>();

    // 4. softmax (sums partials, applies norms)
    softmax_kernel<<<16 * 128, 128>>>(temp);

    // 5. M = Wout_h @ attn_h
    k_M<<<dim3(1, 8, 16), 128, SMEM_S>>>();

    // 6. P = M @ Wv
    k_P<<<dim3(4, 8, Bn), 128, SMEM_S>>>();

    // 7. out = x @ P^T + bias
    k_out<<<dim3(4, 64, Bn), 128, BIG_SMEM>>>(out, bout);
}

// round 16
// speedup vs baseline: 1.6507x; 1.0274x over previous
#include <cuda_runtime.h>
#include <cuda_fp16.h>
#include <cstddef>
#include <cstdint>

#define Bn   4
#define Nn   8192
#define Cn   512
#define DHn  128
#define GSPL 8

// ---------------- scratch (device globals) ---------------------------------
__device__ __align__(128) __half g_xh  [(size_t)Bn * Nn * Cn];
__device__ __align__(128) __half g_xt  [(size_t)Bn * Cn * Nn];
__device__ __align__(128) __half g_wqk2[1024 * 1024];
__device__ __align__(128) __half g_woh [512 * 512];
__device__ __align__(128) __half g_wvt [512 * 512];
__device__ __align__(128) float  g_gramP[(size_t)Bn * GSPL * 512 * 512];
__device__ __align__(128) __half g_g2  [Bn * 512 * 1024];
__device__ __align__(128) __half g_T1  [Bn * 1024 * 512];
__device__ __align__(128) float  g_diag[Bn * 1024];
__device__ __align__(128) float  g_qkP [4 * 16 * DHn * DHn];
__device__ __align__(128) __half g_attnT[16 * DHn * DHn];
__device__ __align__(128) __half g_M   [Bn * Cn * Cn];
__device__ __align__(128) __half g_P   [Bn * Cn * Cn];

__device__ const int c_ti[10] = {0,0,0,0,1,1,1,2,2,3};
__device__ const int c_tj[10] = {0,1,2,3,1,2,3,2,3,3};

// ---------------- PTX helpers ----------------------------------------------
__device__ __forceinline__ uint32_t sptr(const void* p) {
    return (uint32_t)__cvta_generic_to_shared(p);
}
#define CPA(dst, src) asm volatile("cp.async.cg.shared.global [%0],[%1],16;\n" \
                                   :: "r"(dst), "l"(src))
#define CPC() asm volatile("cp.async.commit_group;\n")
#define CPW0() asm volatile("cp.async.wait_group 0;\n")
#define CPW1() asm volatile("cp.async.wait_group 1;\n")

__device__ __forceinline__ void ldmx4(uint32_t* r, uint32_t a) {
    asm volatile("ldmatrix.sync.aligned.m8n8.x4.shared.b16 {%0,%1,%2,%3},[%4];"
                 : "=r"(r[0]), "=r"(r[1]), "=r"(r[2]), "=r"(r[3]) : "r"(a));
}
__device__ __forceinline__ void mma16816(float* c, const uint32_t* a, const uint32_t* b) {
    asm volatile(
        "mma.sync.aligned.m16n8k16.row.col.f32.f16.f16.f32 "
        "{%0,%1,%2,%3},{%4,%5,%6,%7},{%8,%9},{%0,%1,%2,%3};"
        : "+f"(c[0]), "+f"(c[1]), "+f"(c[2]), "+f"(c[3])
        : "r"(a[0]), "r"(a[1]), "r"(a[2]), "r"(a[3]), "r"(b[0]), "r"(b[1]));
}

// ---------------------------------------------------------------------------
// Variant L256: 128x128 CTA tile, 256 threads = 8 warps of 32x64.
// BK=64, 2-stage ring, one barrier/iter. 2 CTAs/SM -> 4 warps per SMSP.
// Stage: A 128x144B (+0), B 128x144B (+18432).
// ---------------------------------------------------------------------------
#define STAGE_BYTES 36864
#define BIG_SMEM    (2 * STAGE_BYTES)   // 73728

#define GEMM_MAINLOOP(A, B, K, lda, ldb, m0, n0)                               \
    const uint32_t s0 = sptr(dsm);                                             \
    const int tid  = threadIdx.x;                                              \
    const int lane = tid & 31;                                                 \
    const int wid  = tid >> 5;                                                 \
    const int wm   = (wid & 3) * 32;                                           \
    const int wn   = (wid >> 2) * 64;                                          \
    float acc[2][8][4];                                                        \
    _Pragma("unroll") for (int i = 0; i < 2; i++)                              \
    _Pragma("unroll") for (int j = 0; j < 8; j++)                              \
    _Pragma("unroll") for (int t = 0; t < 4; t++) acc[i][j][t] = 0.f;          \
    const int lrow = tid >> 3;           /* 0..31 */                           \
    const int lc16 = tid & 7;                                                  \
    const __half* Ag = (A) + (size_t)((m0) + lrow) * (lda) + lc16 * 8;         \
    const __half* Bg = (B) + (size_t)((n0) + lrow) * (ldb) + lc16 * 8;         \
    auto load_stage = [&](int stg, int k0) {                                   \
        const uint32_t ad = s0 + stg * STAGE_BYTES + lrow * 144 + lc16 * 16;   \
        const uint32_t bd = ad + 18432;                                        \
        _Pragma("unroll") for (int u = 0; u < 4; u++) {                        \
            CPA(ad + u * (32 * 144), Ag + (size_t)(u * 32) * (lda) + k0);      \
            CPA(bd + u * (32 * 144), Bg + (size_t)(u * 32) * (ldb) + k0);      \
        }                                                                      \
        CPC();                                                                 \
    };                                                                         \
    const uint32_t a_fb = (wm + (lane & 15)) * 144 + (lane >> 4) * 16;         \
    const uint32_t b_fb = 18432 +                                              \
        (wn + (lane & 7) + ((lane >> 4) * 8)) * 144 + ((lane >> 3) & 1) * 16;  \
    uint32_t af[2][2][4], bf[2][4][4];                                         \
    auto ldfrags = [&](int slot, int stg, int ks) {                            \
        const uint32_t ab = s0 + stg * STAGE_BYTES + a_fb + ks * 32;           \
        const uint32_t bb = s0 + stg * STAGE_BYTES + b_fb + ks * 32;           \
        _Pragma("unroll") for (int mi = 0; mi < 2; mi++)                       \
            ldmx4(af[slot][mi], ab + mi * (16 * 144));                         \
        _Pragma("unroll") for (int nj = 0; nj < 4; nj++)                       \
            ldmx4(bf[slot][nj], bb + nj * (16 * 144));                         \
    };                                                                         \
    auto mma_all = [&](int slot) {                                             \
        _Pragma("unroll") for (int mi = 0; mi < 2; mi++)                       \
        _Pragma("unroll") for (int nj = 0; nj < 8; nj++)                       \
            mma16816(acc[mi][nj], af[slot][mi], &bf[slot][nj >> 1][(nj & 1) * 2]); \
    };                                                                         \
    const int niter = (K) / 64;                                                \
    load_stage(0, 0);                                                          \
    load_stage(1, 64);                                                         \
    CPW1();                                                                    \
    __syncthreads();                                                           \
    ldfrags(0, 0, 0);                                                          \
    int st = 0;                                                                \
    for (int it = 0; it < niter; ++it) {                                       \
        ldfrags(1, st, 1); mma_all(0);                                         \
        ldfrags(0, st, 2); mma_all(1);                                         \
        ldfrags(1, st, 3); mma_all(0);                                         \
        if (it + 1 < niter) {                                                  \
            CPW0();                                                            \
            __syncthreads();                                                   \
            if (it + 2 < niter) load_stage(st, (it + 2) * 64);                 \
            ldfrags(0, st ^ 1, 0);                                             \
            st ^= 1;                                                           \
        }                                                                      \
        mma_all(1);                                                            \
    }

template<bool HALF_OUT, bool BIAS>
__device__ __forceinline__ void gemm_big(
    const __half* __restrict__ A, const __half* __restrict__ B,
    void* __restrict__ Cp, const float* __restrict__ bias,
    int K, int lda, int ldb, int ldc, int m0, int n0)
{
    extern __shared__ char dsm[];
    GEMM_MAINLOOP(A, B, K, lda, ldb, m0, n0)

    const int g  = lane >> 2;
    const int tg = lane & 3;
#pragma unroll
    for (int mi = 0; mi < 2; mi++) {
#pragma unroll
        for (int nj = 0; nj < 8; nj++) {
            const int r0 = m0 + wm + mi * 16 + g;
            const int cc = n0 + wn + nj * 8 + 2 * tg;
            float* a4 = acc[mi][nj];
            if (HALF_OUT) {
                __half* C = (__half*)Cp;
                *(__half2*)&C[(size_t)r0 * ldc + cc]       = __floats2half2_rn(a4[0], a4[1]);
                *(__half2*)&C[(size_t)(r0 + 8) * ldc + cc] = __floats2half2_rn(a4[2], a4[3]);
            } else {
                float* C = (float*)Cp;
                float b0 = 0.f, b1 = 0.f;
                if (BIAS) { float2 bb = *(const float2*)&bias[cc]; b0 = bb.x; b1 = bb.y; }
                *(float2*)&C[(size_t)r0 * ldc + cc]       = make_float2(a4[0] + b0, a4[1] + b1);
                *(float2*)&C[(size_t)(r0 + 8) * ldc + cc] = make_float2(a4[2] + b0, a4[3] + b1);
            }
        }
    }
}

// ---------------------------------------------------------------------------
// Variant S: 64x128 CTA tile (latency kernels: k_T1, k_qkp, k_M, k_P)
// ---------------------------------------------------------------------------
#define STAGE_S  27648
#define SMEM_S   (2 * STAGE_S)   // 55296

#define GEMM_MAINLOOP_S(A, B, K, lda, ldb, m0, n0)                             \
    const uint32_t s0 = sptr(dsm);                                             \
    const int tid  = threadIdx.x;                                              \
    const int lane = tid & 31;                                                 \
    const int wid  = tid >> 5;                                                 \
    const int wn   = wid * 32;                                                 \
    float acc[4][4][4];                                                        \
    _Pragma("unroll") for (int i = 0; i < 4; i++)                              \
    _Pragma("unroll") for (int j = 0; j < 4; j++)                              \
    _Pragma("unroll") for (int t = 0; t < 4; t++) acc[i][j][t] = 0.f;          \
    const int lrow = tid >> 3;                                                 \
    const int lc16 = tid & 7;                                                  \
    const __half* Ag = (A) + (size_t)((m0) + lrow) * (lda) + lc16 * 8;         \
    const __half* Bg = (B) + (size_t)((n0) + lrow) * (ldb) + lc16 * 8;         \
    auto load_stage = [&](int stg, int k0) {                                   \
        const uint32_t ad = s0 + stg * STAGE_S + lrow * 144 + lc16 * 16;       \
        const uint32_t bd = ad + 9216;                                         \
        _Pragma("unroll") for (int u = 0; u < 4; u++)                          \
            CPA(ad + u * (16 * 144), Ag + (size_t)(u * 16) * (lda) + k0);      \
        _Pragma("unroll") for (int u = 0; u < 8; u++)                          \
            CPA(bd + u * (16 * 144), Bg + (size_t)(u * 16) * (ldb) + k0);      \
        CPC();                                                                 \
    };                                                                         \
    const uint32_t a_fb = (lane & 15) * 144 + (lane >> 4) * 16;                \
    const uint32_t b_fb = 9216 +                                               \
        (wn + (lane & 7) + ((lane >> 4) * 8)) * 144 + ((lane >> 3) & 1) * 16;  \
    uint32_t af[2][4][4], bf[2][2][4];                                         \
    auto ldfrags = [&](int slot, int stg, int ks) {                            \
        const uint32_t ab = s0 + stg * STAGE_S + a_fb + ks * 32;               \
        const uint32_t bb = s0 + stg * STAGE_S + b_fb + ks * 32;               \
        _Pragma("unroll") for (int mi = 0; mi < 4; mi++)                       \
            ldmx4(af[slot][mi], ab + mi * (16 * 144));                         \
        _Pragma("unroll") for (int nj = 0; nj < 2; nj++)                       \
            ldmx4(bf[slot][nj], bb + nj * (16 * 144));                         \
    };                                                                         \
    auto mma_all = [&](int slot) {                                             \
        _Pragma("unroll") for (int mi = 0; mi < 4; mi++)                       \
        _Pragma("unroll") for (int nj = 0; nj < 4; nj++)                       \
            mma16816(acc[mi][nj], af[slot][mi], &bf[slot][nj >> 1][(nj & 1) * 2]); \
    };                                                                         \
    const int niter = (K) / 64;                                                \
    load_stage(0, 0);                                                          \
    load_stage(1, 64);                                                         \
    CPW1();                                                                    \
    __syncthreads();                                                           \
    ldfrags(0, 0, 0);                                                          \
    int st = 0;                                                                \
    for (int it = 0; it < niter; ++it) {                                       \
        ldfrags(1, st, 1); mma_all(0);                                         \
        ldfrags(0, st, 2); mma_all(1);                                         \
        ldfrags(1, st, 3); mma_all(0);                                         \
        if (it + 1 < niter) {                                                  \
            CPW0();                                                            \
            __syncthreads();                                                   \
            if (it + 2 < niter) load_stage(st, (it + 2) * 64);                 \
            ldfrags(0, st ^ 1, 0);                                             \
            st ^= 1;                                                           \
        }                                                                      \
        mma_all(1);                                                            \
    }

template<bool HALF_OUT>
__device__ __forceinline__ void gemm_small(
    const __half* __restrict__ A, const __half* __restrict__ B,
    void* __restrict__ Cp,
    int K, int lda, int ldb, int ldc, int m0, int n0)
{
    extern __shared__ char dsm[];
    GEMM_MAINLOOP_S(A, B, K, lda, ldb, m0, n0)

    const int g  = lane >> 2;
    const int tg = lane & 3;
#pragma unroll
    for (int mi = 0; mi < 4; mi++) {
#pragma unroll
        for (int nj = 0; nj < 4; nj++) {
            const int r0 = m0 + mi * 16 + g;
            const int cc = n0 + wn + nj * 8 + 2 * tg;
            float* a4 = acc[mi][nj];
            if (HALF_OUT) {
                __half* C = (__half*)Cp;
                *(__half2*)&C[(size_t)r0 * ldc + cc]       = __floats2half2_rn(a4[0], a4[1]);
                *(__half2*)&C[(size_t)(r0 + 8) * ldc + cc] = __floats2half2_rn(a4[2], a4[3]);
            } else {
                float* C = (float*)Cp;
                *(float2*)&C[(size_t)r0 * ldc + cc]       = make_float2(a4[0], a4[1]);
                *(float2*)&C[(size_t)(r0 + 8) * ldc + cc] = make_float2(a4[2], a4[3]);
            }
        }
    }
}

// ---------------- GEMM kernels -----------------------------------------------
// 1. Gram partials (upper-triangle tiles): grid (GSPL, 10, 4), 256 thr
__global__ void __launch_bounds__(256, 2) k_gram()
{
    const int b = blockIdx.z;
    const int m0 = c_ti[blockIdx.y] * 128;
    const int n0 = c_tj[blockIdx.y] * 128;
    const __half* X = g_xt + (size_t)b * Cn * Nn + (size_t)blockIdx.x * (Nn / GSPL);
    float* C = g_gramP + ((size_t)b * GSPL + blockIdx.x) * (512 * 512);
    gemm_big<false, false>(X, X, C, nullptr, Nn / GSPL, Nn, Nn, 512, m0, n0);
}

// 2. T1 = Wqk @ G (hi+lo), half out.  grid (4 nt, 16 mt, 4 b), S-variant.
__global__ void __launch_bounds__(128, 3) k_T1()
{
    const int b = blockIdx.z;
    const __half* Bg = g_g2 + (size_t)b * 512 * 1024;
    __half* C = g_T1 + (size_t)b * 1024 * 512;
    gemm_small<true>(g_wqk2, Bg, C, 1024, 1024, 1024, 512,
                     blockIdx.y * 64, blockIdx.x * 128);
}

// 3a. diag dots (warp per row)
__global__ void __launch_bounds__(256) kdiag()
{
    const int gw = blockIdx.x * 8 + (threadIdx.x >> 5);
    const int b = gw >> 10, r = gw & 1023;
    const int lane = threadIdx.x & 31;
    const __half2* t1 = (const __half2*)(g_T1 + ((size_t)b * 1024 + r) * 512);
    const __half2* wr = (const __half2*)(g_wqk2 + (size_t)r * 1024);
    float s = 0.f;
#pragma unroll
    for (int k = lane; k < 256; k += 32) {
        float2 a = __half22float2(t1[k]);
        float2 w = __half22float2(wr[k]);
        s = fmaf(a.x, w.x, fmaf(a.y, w.y, s));
    }
#pragma unroll
    for (int off = 16; off; off >>= 1)
        s += __shfl_xor_sync(0xffffffffu, s, off);
    if (lane == 0) g_diag[gw] = s;
}

// 3b. QK logits split-K partials: grid (4 splits, 2 mt, 16 bh), S, K=128
__global__ void __launch_bounds__(128, 3) k_qkp()
{
    const int s4 = blockIdx.x;
    const int mt = blockIdx.y;
    const int bh = blockIdx.z;
    const int b = bh >> 2, h = bh & 3;
    const __half* A = g_T1 + (size_t)b * 1024 * 512
                    + (size_t)(h * DHn + mt * 64) * 512 + s4 * 128;
    const __half* Bp = g_wqk2 + (size_t)(512 + h * DHn) * 1024 + s4 * 128;
    float* C = g_qkP + ((size_t)s4 * 16 + bh) * (DHn * DHn) + mt * 64 * DHn;
    gemm_small<false>(A, Bp, C, 128, 512, 1024, DHn, 0, 0);
}

// 4. softmax over d: sum partials + normalize; writes attnT[bh][d][c]
__global__ void __launch_bounds__(128) softmax_kernel(const float* __restrict__ temp)
{
    const int bh = blockIdx.x >> 7;
    const int c  = blockIdx.x & 127;
    const int b  = bh >> 2, h = bh & 3;
    const int d  = threadIdx.x;

    float s = 0.f;
#pragma unroll
    for (int p = 0; p < 4; p++)
        s += g_qkP[((size_t)p * 16 + bh) * (DHn * DHn) + c * DHn + d];

    const float qq = g_diag[b * 1024 + h * DHn + c];
    const float kk = g_diag[b * 1024 + 512 + h * DHn + d];
    const float qinv = 1.f / fmaxf(sqrtf(fmaxf(qq, 0.f)), 1e-12f);
    const float kinv = 1.f / fmaxf(sqrtf(fmaxf(kk, 0.f)), 1e-12f);
    const float val  = s * qinv * kinv * temp[h];

    __shared__ float red[128];
    red[d] = val;
    __syncthreads();
    for (int off = 64; off; off >>= 1) {
        if (d < off) red[d] = fmaxf(red[d], red[d + off]);
        __syncthreads();
    }
    const float mx = red[0];
    __syncthreads();
    const float e = expf(val - mx);
    red[d] = e;
    __syncthreads();
    for (int off = 64; off; off >>= 1) {
        if (d < off) red[d] += red[d + off];
        __syncthreads();
    }
    g_attnT[(size_t)bh * (DHn * DHn) + d * DHn + c] = __float2half_rn(e / red[0]);
}

// 5. M_b[j][h*128+d] = Wout_h @ attn_bh   grid (1, 8 mt, 16 bh), S, K=128
__global__ void __launch_bounds__(128, 3) k_M()
{
    const int bh = blockIdx.z;
    const int b = bh >> 2, h = bh & 3;
    const __half* A  = g_woh + h * DHn;
    const __half* Bt = g_attnT + (size_t)bh * DHn * DHn;
    __half* C = g_M + (size_t)b * Cn * Cn + h * DHn;
    gemm_small<true>(A, Bt, C, DHn, 512, DHn, Cn, blockIdx.y * 64, 0);
}

// 6. P_b = M_b @ Wv, half out. grid (4 nt, 8 mt, 4 b), S, K=512
__global__ void __launch_bounds__(128, 3) k_P()
{
    const int b = blockIdx.z;
    const __half* A = g_M + (size_t)b * Cn * Cn;
    __half* C = g_P + (size_t)b * Cn * Cn;
    gemm_small<true>(A, g_wvt, C, 512, 512, 512, 512,
                     blockIdx.y * 64, blockIdx.x * 128);
}

// 7. out = x @ P^T + bias   grid (4, 64, 4), L256-variant
__global__ void __launch_bounds__(256, 2) k_out(float* __restrict__ out,
                                                const float* __restrict__ bias)
{
    const int b = blockIdx.z;
    const __half* A = g_xh + (size_t)b * Nn * Cn;
    const __half* Bp = g_P + (size_t)b * Cn * Cn;
    float* C = out + (size_t)b * Nn * Cn;
    gemm_big<false, true>(A, Bp, C, bias, 512, 512, 512, 512,
                          blockIdx.y * 128, blockIdx.x * 128);
}

// ---------------- small kernels ---------------------------------------------
__global__ void __launch_bounds__(256) xprep(const float* __restrict__ x)
{
    __shared__ __half ts[32][33];
    const int n0 = blockIdx.x * 32, c0 = blockIdx.y * 32, b = blockIdx.z;
    const int tx = threadIdx.x, ty = threadIdx.y;
#pragma unroll
    for (int r = 0; r < 4; r++) {
        const size_t idx = ((size_t)b * Nn + n0 + ty + r * 8) * Cn + c0 + tx;
        const __half hv = __float2half_rn(x[idx]);
        g_xh[idx] = hv;
        ts[ty + r * 8][tx] = hv;
    }
    __syncthreads();
#pragma unroll
    for (int r = 0; r < 4; r++)
        g_xt[((size_t)b * Cn + c0 + ty + r * 8) * Nn + n0 + tx] = ts[tx][ty + r * 8];
}

__global__ void __launch_bounds__(256) wprep(const float* __restrict__ Wqkv,
                                             const float* __restrict__ Wout)
{
    const int idx = blockIdx.x * 256 + threadIdx.x;
    if (idx < 1024 * 1024) {
        const int m = idx >> 10, k = idx & 1023;
        g_wqk2[idx] = __float2half_rn(Wqkv[m * 512 + (k & 511)]);
    } else if (idx < 1024 * 1024 + 262144) {
        const int t = idx - 1024 * 1024;
        g_woh[t] = __float2half_rn(Wout[t]);
    } else {
        const int t = idx - 1024 * 1024 - 262144;
        const int j = t >> 9, m = t & 511;
        g_wvt[t] = __float2half_rn(Wqkv[(1024 + m) * 512 + j]);
    }
}

// reduce gram partials -> hi/lo fp16 pair, coalesced mirror
__global__ void __launch_bounds__(256) gred_t()
{
    __shared__ float sh[32][33];
    const int b  = blockIdx.z;
    const int ti = c_ti[blockIdx.y], tj = c_tj[blockIdx.y];
    const int si = (blockIdx.x >> 2) * 32, sj = (blockIdx.x & 3) * 32;
    const int i0 = ti * 128 + si, j0 = tj * 128 + sj;
    const int tx = threadIdx.x, ty = threadIdx.y;
    const float* gp = g_gramP + (size_t)b * GSPL * 262144;

#pragma unroll
    for (int r = 0; r < 4; r++) {
        const int i = i0 + ty + r * 8;
        const int j = j0 + tx;
        float s = 0.f;
#pragma unroll
        for (int p = 0; p < GSPL; p++)
            s += gp[(size_t)p * 262144 + i * 512 + j];
        const __half hi = __float2half_rn(s);
        g_g2[((size_t)b * 512 + i) * 1024 + j]       = hi;
        g_g2[((size_t)b * 512 + i) * 1024 + 512 + j] =
            __float2half_rn(s - __half2float(hi));
        sh[ty + r * 8][tx] = s;
    }
    if (ti == tj) return;
    __syncthreads();
#pragma unroll
    for (int r = 0; r < 4; r++) {
        const int jj = j0 + ty + r * 8;
        const int ii = i0 + tx;
        const float s = sh[tx][ty + r * 8];
        const __half hi = __float2half_rn(s);
        g_g2[((size_t)b * 512 + jj) * 1024 + ii]       = hi;
        g_g2[((size_t)b * 512 + jj) * 1024 + 512 + ii] =
            __float2half_rn(s - __half2float(hi));
    }
}

// ---------------------------------------------------------------------------
extern "C" void kernel_launch(void* const* d_in, const int* in_sizes, int n_in,
                              void* d_out, int out_size)
{
    const float* x    = (const float*)d_in[0];
    const float* Wqkv = (const float*)d_in[1];
    const float* Wout = (const float*)d_in[2];
    const float* bout = (const float*)d_in[3];
    const float* temp = (const float*)d_in[4];
    float* out = (float*)d_out;

    cudaFuncSetAttribute(k_gram, cudaFuncAttributeMaxDynamicSharedMemorySize, BIG_SMEM);
    cudaFuncSetAttribute(k_out,  cudaFuncAttributeMaxDynamicSharedMemorySize, BIG_SMEM);
    cudaFuncSetAttribute(k_T1,   cudaFuncAttributeMaxDynamicSharedMemorySize, SMEM_S);
    cudaFuncSetAttribute(k_qkp,  cudaFuncAttributeMaxDynamicSharedMemorySize, SMEM_S);
    cudaFuncSetAttribute(k_M,    cudaFuncAttributeMaxDynamicSharedMemorySize, SMEM_S);
    cudaFuncSetAttribute(k_P,    cudaFuncAttributeMaxDynamicSharedMemorySize, SMEM_S);

    // 0. conversions / layouts
    xprep<<<dim3(Nn / 32, Cn / 32, Bn), dim3(32, 8)>>>(x);
    wprep<<<6144, 256>>>(Wqkv, Wout);

    // 1. Gram partials (triangle) + coalesced reduce/mirror/split
    k_gram<<<dim3(GSPL, 10, Bn), 256, BIG_SMEM>>>();
    gred_t<<<dim3(16, 10, Bn), dim3(32, 8)>>>();

    // 2. T1 = Wqk @ G (hi+lo), latency-shaped
    k_T1<<<dim3(4, 16, Bn), 128, SMEM_S>>>();

    // 3. diagonal norms + split-K logits partials
    kdiag<<<512, 256>>>();
    k_qkp<<<dim3(4, 2, 16), 128, SMEM_S>>>();

    // 4. softmax (sums partials, applies norms)
    softmax_kernel<<<16 * 128, 128>>>(temp);

    // 5. M = Wout_h @ attn_h
    k_M<<<dim3(1, 8, 16), 128, SMEM_S>>>();

    // 6. P = M @ Wv
    k_P<<<dim3(4, 8, Bn), 128, SMEM_S>>>();

    // 7. out = x @ P^T + bias
    k_out<<<dim3(4, 64, Bn), 256, BIG_SMEM>>>(out, bout);
}